// round 12
// baseline (speedup 1.0000x reference)
#include <cuda_runtime.h>
#include <cuda_fp16.h>
#include <math.h>
#include <stdint.h>

#define N_NODES 50000
#define N_EDGES 800000
#define EMB 128
#define NFEAT 7
#define EFEAT 5
#define HID 256
#define CDIV(a,b) (((a)+(b)-1)/(b))

// ---------------- scratch (static device allocations) ----------------
__device__ __align__(16) float  g_h[N_NODES * EMB];      // h (post-BN) / z (post-GEMM2)
__device__ __align__(16) __half g_th[N_NODES * HID];     // hidden hi
__device__ __align__(16) __half g_tl[N_NODES * HID];     // hidden lo
__device__ __align__(16) __half g_W1h[5 * HID * EMB];    // W1^T hi: [l][n=256][k=128]
__device__ __align__(16) __half g_W1l[5 * HID * EMB];
__device__ __align__(16) __half g_W2h[5 * EMB * HID];    // W2^T hi: [l][n=128][k=256]
__device__ __align__(16) __half g_W2l[5 * EMB * HID];
__device__ int   g_cnt[N_NODES];
__device__ int   g_rowptr[N_NODES + 1];
__device__ int   g_cur[N_NODES];
__device__ int   g_eid[N_EDGES];
__device__ int   g_src[N_EDGES];            // dst-sorted source node ids
__device__ float g_sea[N_NODES * EFEAT];    // per-node sum of edge_attr over in-edges
__device__ float g_colsum[EMB];
__device__ float g_colsq[EMB];

// ---------------- helpers ----------------
__device__ __forceinline__ uint32_t smem_u32(const void* p) {
  uint32_t a;
  asm("{ .reg .u64 t; cvta.to.shared.u64 t, %1; cvt.u32.u64 %0, t; }" : "=r"(a) : "l"(p));
  return a;
}
__device__ __forceinline__ void cp16(uint32_t dst, const void* src, int sz) {
  asm volatile("cp.async.cg.shared.global [%0], [%1], 16, %2;"
               :: "r"(dst), "l"(src), "r"(sz));
}
__device__ __forceinline__ void ldsm4(uint32_t* r, uint32_t addr) {
  asm volatile("ldmatrix.sync.aligned.m8n8.x4.shared.b16 {%0,%1,%2,%3}, [%4];"
               : "=r"(r[0]), "=r"(r[1]), "=r"(r[2]), "=r"(r[3]) : "r"(addr));
}
__device__ __forceinline__ void mma_f16(float* d, const uint32_t* a, const uint32_t* b) {
  asm volatile(
    "mma.sync.aligned.m16n8k16.row.col.f32.f16.f16.f32 "
    "{%0,%1,%2,%3}, {%4,%5,%6,%7}, {%8,%9}, {%0,%1,%2,%3};"
    : "+f"(d[0]), "+f"(d[1]), "+f"(d[2]), "+f"(d[3])
    : "r"(a[0]), "r"(a[1]), "r"(a[2]), "r"(a[3]), "r"(b[0]), "r"(b[1]));
}
__device__ __forceinline__ void split1(float v, __half& h, __half& l) {
  h = __float2half_rn(v);
  l = __float2half_rn(v - __half2float(h));
}

// ---------------- CSR build ----------------
__global__ void k_zero_cnt() {
  int i = blockIdx.x * 256 + threadIdx.x;
  if (i < N_NODES) g_cnt[i] = 0;
}

__global__ void k_hist(const int* __restrict__ ei) {
  int e = blockIdx.x * 256 + threadIdx.x;
  if (e < N_EDGES) atomicAdd(&g_cnt[ei[N_EDGES + e]], 1);
}

__global__ void k_scan() {  // single block, 1024 threads
  __shared__ int sums[1024];
  int t = threadIdx.x;
  const int CH = (N_NODES + 1023) / 1024;
  int base = t * CH;
  int s = 0;
  for (int i = 0; i < CH; i++) {
    int idx = base + i;
    if (idx < N_NODES) s += g_cnt[idx];
  }
  sums[t] = s;
  __syncthreads();
  for (int off = 1; off < 1024; off <<= 1) {
    int v = (t >= off) ? sums[t - off] : 0;
    __syncthreads();
    sums[t] += v;
    __syncthreads();
  }
  int run = (t == 0) ? 0 : sums[t - 1];
  for (int i = 0; i < CH; i++) {
    int idx = base + i;
    if (idx < N_NODES) {
      g_rowptr[idx] = run;
      g_cur[idx]    = run;
      run += g_cnt[idx];
    }
  }
  if (t == 1023) g_rowptr[N_NODES] = run;
}

__global__ void k_fill(const int* __restrict__ ei) {
  int e = blockIdx.x * 256 + threadIdx.x;
  if (e < N_EDGES) {
    int dst = ei[N_EDGES + e];
    int p = atomicAdd(&g_cur[dst], 1);
    g_eid[p] = e;
  }
}

// g_src[p] = src of dst-sorted edge p; g_sea[node] = sum of edge_attr over in-edges.
__global__ __launch_bounds__(256) void k_prep_graph(const int* __restrict__ ei,
                                                    const float* __restrict__ ea) {
  int node = blockIdx.x * 8 + (threadIdx.x >> 5);
  if (node >= N_NODES) return;
  int lane = threadIdx.x & 31;
  int beg = g_rowptr[node], end = g_rowptr[node + 1];
  float s0 = 0.f, s1 = 0.f, s2 = 0.f, s3 = 0.f, s4 = 0.f;
  for (int p = beg + lane; p < end; p += 32) {
    int e = g_eid[p];
    g_src[p] = ei[e];
    const float* a = ea + (size_t)e * EFEAT;
    s0 += a[0]; s1 += a[1]; s2 += a[2]; s3 += a[3]; s4 += a[4];
  }
#pragma unroll
  for (int off = 16; off > 0; off >>= 1) {
    s0 += __shfl_xor_sync(0xffffffffu, s0, off);
    s1 += __shfl_xor_sync(0xffffffffu, s1, off);
    s2 += __shfl_xor_sync(0xffffffffu, s2, off);
    s3 += __shfl_xor_sync(0xffffffffu, s3, off);
    s4 += __shfl_xor_sync(0xffffffffu, s4, off);
  }
  if (lane == 0) {
    float* d = g_sea + (size_t)node * EFEAT;
    d[0] = s0; d[1] = s1; d[2] = s2; d[3] = s3; d[4] = s4;
  }
}

// ---------------- weight transpose + split: W[K,N] -> Wt[N,K] hi/lo ----------------
__global__ void k_prep_w(const float* __restrict__ W1, const float* __restrict__ W2) {
  int idx = blockIdx.x * 256 + threadIdx.x;
  const int T = 5 * 128 * 256;
  if (idx < T) {
    int k = idx & 127, n = (idx >> 7) & 255, l = idx >> 15;
    float v = W1[l * 32768 + k * 256 + n];
    __half h, lo; split1(v, h, lo);
    g_W1h[idx] = h; g_W1l[idx] = lo;
  } else if (idx < 2 * T) {
    int j = idx - T;
    int k = j & 255, n = (j >> 8) & 127, l = j >> 15;
    float v = W2[l * 32768 + k * 128 + n];
    __half h, lo; split1(v, h, lo);
    g_W2h[j] = h; g_W2l[j] = lo;
  }
}

// ---------------- initial node embedding (fp32 h) ----------------
__global__ void k_init_h(const float* __restrict__ x, const float* __restrict__ Wx,
                         const float* __restrict__ bx) {
  __shared__ float xs[NFEAT];
  int i = blockIdx.x;
  int c = threadIdx.x;
  if (c < NFEAT) xs[c] = x[i * NFEAT + c];
  __syncthreads();
  float acc = 0.f;
#pragma unroll
  for (int f = 0; f < NFEAT; f++) acc += xs[f] * Wx[f * EMB + c];
#pragma unroll
  for (int f = 0; f < NFEAT; f++) acc += bx[f * EMB + c];
  g_h[(size_t)i * EMB + c] = acc;
}

// ---------------- fused gather + GEMM1 ----------------
// Phase A: agg[128 rows] computed in-CTA (reads fp32 g_h), hi/lo split written directly
//          into ldmatrix-swizzled smem (K=128 resident).
// Phase B: hidden = relu(agg @ W1^T + b1), two 128-col passes, B double-buffered.
// smem map (bytes): [0,32768) Ah | [32768,65536) Al | [65536,98304) B 2 bufs x (Bh 8K | Bl 8K)
//                   [98304,100864) sWe | [100864,101376) sbe
#define F1_SMEM 101376
__global__ __launch_bounds__(256, 2) void k_fused1(int layer,
                                                   const float* __restrict__ We,
                                                   const float* __restrict__ be,
                                                   const float* __restrict__ bias) {
  extern __shared__ float smf[];
  char* smc = (char*)smf;
  float* sWe = (float*)(smc + 98304);
  float* sbe = sWe + EFEAT * EMB;
  const uint32_t sbase = smem_u32(smf);

  const int tid  = threadIdx.x;
  const int lane = tid & 31;
  const int wid  = tid >> 5;
  const int brow = blockIdx.x * 128;

  if (blockIdx.x == 0 && tid < EMB) { g_colsum[tid] = 0.f; g_colsq[tid] = 0.f; }
  for (int i = tid; i < EFEAT * EMB; i += 256) sWe[i] = We[i];
  if (tid < EMB) {
    float s = 0.f;
#pragma unroll
    for (int f = 0; f < EFEAT; f++) s += be[f * EMB + tid];
    sbe[tid] = s;
  }
  __syncthreads();

  // ---- Phase A: gather ----
  {
    const int c = lane * 4;
    const uint32_t kb = (uint32_t)(c >> 4);
    const uint32_t kh = (uint32_t)((c >> 3) & 1);
    for (int ln = wid; ln < 128; ln += 8) {
      int node = brow + ln;
      float4 acc = make_float4(0.f, 0.f, 0.f, 0.f);
      if (node < N_NODES) {
        acc = *(const float4*)(g_h + (size_t)node * EMB + c);
        int beg = g_rowptr[node], end = g_rowptr[node + 1];
        float cnt1 = (float)(end - beg + 1);
        acc.x += cnt1 * sbe[c + 0];
        acc.y += cnt1 * sbe[c + 1];
        acc.z += cnt1 * sbe[c + 2];
        acc.w += cnt1 * sbe[c + 3];
        {
          float sv = (lane < EFEAT) ? g_sea[(size_t)node * EFEAT + lane] : 0.f;
          float s0 = __shfl_sync(0xffffffffu, sv, 0);
          float s1 = __shfl_sync(0xffffffffu, sv, 1);
          float s2 = __shfl_sync(0xffffffffu, sv, 2);
          float s3 = __shfl_sync(0xffffffffu, sv, 3);
          float s4 = __shfl_sync(0xffffffffu, sv, 4);
          acc.x += s0*sWe[c+0] + s1*sWe[128+c+0] + s2*sWe[256+c+0] + s3*sWe[384+c+0] + s4*sWe[512+c+0];
          acc.y += s0*sWe[c+1] + s1*sWe[128+c+1] + s2*sWe[256+c+1] + s3*sWe[384+c+1] + s4*sWe[512+c+1];
          acc.z += s0*sWe[c+2] + s1*sWe[128+c+2] + s2*sWe[256+c+2] + s3*sWe[384+c+2] + s4*sWe[512+c+2];
          acc.w += s0*sWe[c+3] + s1*sWe[128+c+3] + s2*sWe[256+c+3] + s3*sWe[384+c+3] + s4*sWe[512+c+3];
        }
        int p = beg;
        while (p < end) {
          int nb = min(32, end - p);
          int s_l = (lane < nb) ? g_src[p + lane] : 0;
          int q = 0;
          for (; q + 4 <= nb; q += 4) {
            int s0 = __shfl_sync(0xffffffffu, s_l, q);
            int s1 = __shfl_sync(0xffffffffu, s_l, q + 1);
            int s2 = __shfl_sync(0xffffffffu, s_l, q + 2);
            int s3 = __shfl_sync(0xffffffffu, s_l, q + 3);
            float4 h0 = *(const float4*)(g_h + (size_t)s0 * EMB + c);
            float4 h1 = *(const float4*)(g_h + (size_t)s1 * EMB + c);
            float4 h2 = *(const float4*)(g_h + (size_t)s2 * EMB + c);
            float4 h3 = *(const float4*)(g_h + (size_t)s3 * EMB + c);
            acc.x += (h0.x + h1.x) + (h2.x + h3.x);
            acc.y += (h0.y + h1.y) + (h2.y + h3.y);
            acc.z += (h0.z + h1.z) + (h2.z + h3.z);
            acc.w += (h0.w + h1.w) + (h2.w + h3.w);
          }
          for (; q < nb; q++) {
            int s0 = __shfl_sync(0xffffffffu, s_l, q);
            float4 h0 = *(const float4*)(g_h + (size_t)s0 * EMB + c);
            acc.x += h0.x; acc.y += h0.y; acc.z += h0.z; acc.w += h0.w;
          }
          p += nb;
        }
      }
      __half h0, l0, h1, l1, h2, l2, h3, l3;
      split1(acc.x, h0, l0); split1(acc.y, h1, l1);
      split1(acc.z, h2, l2); split1(acc.w, h3, l3);
      uint32_t off = kb * 4096u + (uint32_t)(ln * 32) +
                     ((kh ^ (uint32_t)((ln >> 2) & 1)) << 4) + (uint32_t)((c & 7) * 2);
      __half2 ph0 = __halves2half2(h0, h1), ph1 = __halves2half2(h2, h3);
      __half2 pl0 = __halves2half2(l0, l1), pl1 = __halves2half2(l2, l3);
      uint2 uh, ul;
      uh.x = *(uint32_t*)&ph0; uh.y = *(uint32_t*)&ph1;
      ul.x = *(uint32_t*)&pl0; ul.y = *(uint32_t*)&pl1;
      *(uint2*)(smc + off)          = uh;
      *(uint2*)(smc + 32768u + off) = ul;
    }
  }
  __syncthreads();

  // ---- Phase B: GEMM over resident A, two 128-col passes ----
  const __half* Bh = g_W1h + (size_t)layer * HID * EMB;
  const __half* Bl = g_W1l + (size_t)layer * HID * EMB;
  const int gid = lane >> 2;
  const int tig = lane & 3;
  const int wm  = wid & 3;
  const int wn  = wid >> 2;
  const int rlan = lane & 15;
  const int khl  = lane >> 4;

  uint32_t aoff[2];
#pragma unroll
  for (int mf = 0; mf < 2; mf++) {
    int row = wm * 32 + mf * 16 + rlan;
    aoff[mf] = (uint32_t)(row * 32) + (uint32_t)((khl ^ ((row >> 2) & 1)) << 4);
  }
  uint32_t boff[4];
#pragma unroll
  for (int g = 0; g < 4; g++) {
    int n = wn * 64 + g * 16 + rlan;
    boff[g] = (uint32_t)(n * 32) + (uint32_t)((khl ^ ((n >> 2) & 1)) << 4);
  }

  for (int pass = 0; pass < 2; pass++) {
    const int bcol = pass * 128;
    float acc[2][8][4];
#pragma unroll
    for (int mf = 0; mf < 2; mf++)
#pragma unroll
      for (int nf = 0; nf < 8; nf++)
#pragma unroll
        for (int j = 0; j < 4; j++) acc[mf][nf][j] = 0.f;

    // B chunk loader: chunk ck covers k in [ck*32, ck*32+32); 128 rows (cols bcol..bcol+127)
    auto load_B = [&](int ck, int b) {
      int k0 = ck * 32;
      uint32_t sbuf = sbase + 65536u + (uint32_t)b * 16384u;
#pragma unroll
      for (int i = 0; i < 2; i++) {
        int j = tid + i * 256;          // 0..511
        int row = j >> 2, q = j & 3;
        int kb2 = q >> 1, kh2 = q & 1;
        uint32_t doff = (uint32_t)kb2 * 4096u + (uint32_t)(row * 32) +
                        (uint32_t)((kh2 ^ ((row >> 2) & 1)) << 4);
        cp16(sbuf + doff,         Bh + (size_t)(bcol + row) * EMB + k0 + q * 8, 16);
        cp16(sbuf + 8192u + doff, Bl + (size_t)(bcol + row) * EMB + k0 + q * 8, 16);
      }
      asm volatile("cp.async.commit_group;");
    };

    load_B(0, 0);
    for (int ck = 0; ck < 4; ck++) {
      int b = ck & 1;
      if (ck + 1 < 4) {
        load_B(ck + 1, b ^ 1);
        asm volatile("cp.async.wait_group 1;");
      } else {
        asm volatile("cp.async.wait_group 0;");
      }
      __syncthreads();
      uint32_t bbuf = sbase + 65536u + (uint32_t)b * 16384u;
#pragma unroll
      for (int kb2 = 0; kb2 < 2; kb2++) {
        uint32_t akb = (uint32_t)(ck * 2 + kb2) * 4096u;
        uint32_t ah[2][4], al[2][4];
#pragma unroll
        for (int mf = 0; mf < 2; mf++) {
          ldsm4(ah[mf], sbase + akb + aoff[mf]);
          ldsm4(al[mf], sbase + 32768u + akb + aoff[mf]);
        }
#pragma unroll
        for (int g = 0; g < 4; g++) {
          uint32_t rh[4], rl[4];
          ldsm4(rh, bbuf + (uint32_t)kb2 * 4096u + boff[g]);
          ldsm4(rl, bbuf + 8192u + (uint32_t)kb2 * 4096u + boff[g]);
          uint32_t b0h[2] = {rh[0], rh[2]}, b1h[2] = {rh[1], rh[3]};
          uint32_t b0l[2] = {rl[0], rl[2]}, b1l[2] = {rl[1], rl[3]};
#pragma unroll
          for (int mf = 0; mf < 2; mf++) {
            mma_f16(acc[mf][2 * g],     ah[mf], b0h);
            mma_f16(acc[mf][2 * g],     ah[mf], b0l);
            mma_f16(acc[mf][2 * g],     al[mf], b0h);
            mma_f16(acc[mf][2 * g + 1], ah[mf], b1h);
            mma_f16(acc[mf][2 * g + 1], ah[mf], b1l);
            mma_f16(acc[mf][2 * g + 1], al[mf], b1h);
          }
        }
      }
      __syncthreads();
    }

    // epilogue: bias + relu + hi/lo split -> g_th/g_tl
#pragma unroll
    for (int mf = 0; mf < 2; mf++) {
      int r0 = brow + wm * 32 + mf * 16 + gid;
#pragma unroll
      for (int nf = 0; nf < 8; nf++) {
        int cg = bcol + wn * 64 + nf * 8 + 2 * tig;
        float b0 = bias[cg], b1v = bias[cg + 1];
        float v0 = fmaxf(acc[mf][nf][0] + b0, 0.f);
        float v1 = fmaxf(acc[mf][nf][1] + b1v, 0.f);
        float v2 = fmaxf(acc[mf][nf][2] + b0, 0.f);
        float v3 = fmaxf(acc[mf][nf][3] + b1v, 0.f);
        __half h0, l0, h1, l1;
        if (r0 < N_NODES) {
          split1(v0, h0, l0); split1(v1, h1, l1);
          size_t i2 = (size_t)r0 * (HID / 2) + (cg >> 1);
          ((__half2*)g_th)[i2] = __halves2half2(h0, h1);
          ((__half2*)g_tl)[i2] = __halves2half2(l0, l1);
        }
        if (r0 + 8 < N_NODES) {
          split1(v2, h0, l0); split1(v3, h1, l1);
          size_t i2 = (size_t)(r0 + 8) * (HID / 2) + (cg >> 1);
          ((__half2*)g_th)[i2] = __halves2half2(h0, h1);
          ((__half2*)g_tl)[i2] = __halves2half2(l0, l1);
        }
      }
    }
    if (pass == 0) __syncthreads();
  }
}

// ---------------- GEMM2: z = hidden @ W2^T + b2, M-tile 64, with BN stats ----------------
// smem per buffer: Ah 4K | Al 4K | Bh 8K | Bl 8K = 24K, x2 buffers = 48K (stats reuse region)
#define G2_SMEM 49152
__global__ __launch_bounds__(256, 2) void k_gemm2(int layer, const float* __restrict__ bias) {
  extern __shared__ float smf[];
  const __half* Ah = g_th;
  const __half* Al = g_tl;
  const __half* Bh = g_W2h + (size_t)layer * EMB * HID;
  const __half* Bl = g_W2l + (size_t)layer * EMB * HID;

  const int tid  = threadIdx.x;
  const int lane = tid & 31;
  const int warp = tid >> 5;
  const int gid  = lane >> 2;
  const int tig  = lane & 3;
  const int wm   = warp & 3;
  const int wn   = warp >> 2;
  const int brow = blockIdx.x * 64;

  const uint32_t sbase = smem_u32(smf);
  constexpr uint32_t AH_SZ = 4096;   // 2 kb x 64 rows x 32B
  constexpr uint32_t BH_SZ = 8192;   // 2 kb x 128 rows x 32B
  constexpr uint32_t BUF   = 2 * AH_SZ + 2 * BH_SZ;  // 24576

  const int rlan = lane & 15;
  const int khl  = lane >> 4;
  uint32_t aoff;
  {
    int row = wm * 16 + rlan;
    aoff = (uint32_t)(row * 32) + (uint32_t)((khl ^ ((row >> 2) & 1)) << 4);
  }
  uint32_t boff[4];
#pragma unroll
  for (int g = 0; g < 4; g++) {
    int n = wn * 64 + g * 16 + rlan;
    boff[g] = (uint32_t)(n * 32) + (uint32_t)((khl ^ ((n >> 2) & 1)) << 4);
  }

  float acc[8][4];
#pragma unroll
  for (int nf = 0; nf < 8; nf++)
#pragma unroll
    for (int j = 0; j < 4; j++) acc[nf][j] = 0.f;

  auto load_chunk = [&](int ck, int b) {
    int k0 = ck * 32;
    uint32_t sbuf = sbase + (uint32_t)b * BUF;
#pragma unroll
    for (int i = 0; i < 3; i++) {
      int j = tid + i * 256;        // 0..767
      if (j < 256) {                // A: 64 rows x 4 q
        int row = j >> 2, q = j & 3;
        int kb = q >> 1, kh = q & 1;
        uint32_t doff = (uint32_t)kb * 2048u + (uint32_t)(row * 32) +
                        (uint32_t)((kh ^ ((row >> 2) & 1)) << 4);
        int ok = (brow + row < N_NODES) ? 16 : 0;
        cp16(sbuf + doff,         Ah + (size_t)(brow + row) * HID + k0 + q * 8, ok);
        cp16(sbuf + AH_SZ + doff, Al + (size_t)(brow + row) * HID + k0 + q * 8, ok);
      } else {                      // B: 128 rows x 4 q
        int jj = j - 256;
        int row = jj >> 2, q = jj & 3;
        int kb = q >> 1, kh = q & 1;
        uint32_t doff = (uint32_t)kb * 4096u + (uint32_t)(row * 32) +
                        (uint32_t)((kh ^ ((row >> 2) & 1)) << 4);
        cp16(sbuf + 2 * AH_SZ + doff,         Bh + (size_t)row * HID + k0 + q * 8, 16);
        cp16(sbuf + 2 * AH_SZ + BH_SZ + doff, Bl + (size_t)row * HID + k0 + q * 8, 16);
      }
    }
    asm volatile("cp.async.commit_group;");
  };

  load_chunk(0, 0);
  for (int ck = 0; ck < 8; ck++) {
    int b = ck & 1;
    if (ck + 1 < 8) {
      load_chunk(ck + 1, b ^ 1);
      asm volatile("cp.async.wait_group 1;");
    } else {
      asm volatile("cp.async.wait_group 0;");
    }
    __syncthreads();
    uint32_t sbuf = sbase + (uint32_t)b * BUF;
#pragma unroll
    for (int kb = 0; kb < 2; kb++) {
      uint32_t ah[4], al[4];
      ldsm4(ah, sbuf + (uint32_t)kb * 2048u + aoff);
      ldsm4(al, sbuf + AH_SZ + (uint32_t)kb * 2048u + aoff);
#pragma unroll
      for (int g = 0; g < 4; g++) {
        uint32_t rh[4], rl[4];
        ldsm4(rh, sbuf + 2 * AH_SZ + (uint32_t)kb * 4096u + boff[g]);
        ldsm4(rl, sbuf + 2 * AH_SZ + BH_SZ + (uint32_t)kb * 4096u + boff[g]);
        uint32_t b0h[2] = {rh[0], rh[2]}, b1h[2] = {rh[1], rh[3]};
        uint32_t b0l[2] = {rl[0], rl[2]}, b1l[2] = {rl[1], rl[3]};
        mma_f16(acc[2 * g],     ah, b0h);
        mma_f16(acc[2 * g],     ah, b0l);
        mma_f16(acc[2 * g],     al, b0h);
        mma_f16(acc[2 * g + 1], ah, b1h);
        mma_f16(acc[2 * g + 1], ah, b1l);
        mma_f16(acc[2 * g + 1], al, b1h);
      }
    }
    __syncthreads();
  }

  // epilogue: bias, write z to g_h, accumulate BN stats
  float ps[8][2], pq[8][2];
#pragma unroll
  for (int nf = 0; nf < 8; nf++) {
    ps[nf][0] = ps[nf][1] = 0.f;
    pq[nf][0] = pq[nf][1] = 0.f;
  }
  int r0 = brow + wm * 16 + gid;
#pragma unroll
  for (int nf = 0; nf < 8; nf++) {
    int cg = wn * 64 + nf * 8 + 2 * tig;
    float b0 = bias[cg], b1v = bias[cg + 1];
    float v0 = acc[nf][0] + b0, v1 = acc[nf][1] + b1v;
    float v2 = acc[nf][2] + b0, v3 = acc[nf][3] + b1v;
    if (r0 < N_NODES) {
      *(float2*)(g_h + (size_t)r0 * EMB + cg) = make_float2(v0, v1);
      ps[nf][0] += v0; pq[nf][0] += v0 * v0;
      ps[nf][1] += v1; pq[nf][1] += v1 * v1;
    }
    if (r0 + 8 < N_NODES) {
      *(float2*)(g_h + (size_t)(r0 + 8) * EMB + cg) = make_float2(v2, v3);
      ps[nf][0] += v2; pq[nf][0] += v2 * v2;
      ps[nf][1] += v3; pq[nf][1] += v3 * v3;
    }
  }
  {
    float* sm_s = smf;                 // [128][32]
    float* sm_q = smf + 128 * 32;      // [128][32]
    __syncthreads();
    int unit = wm * 8 + gid;
#pragma unroll
    for (int nf = 0; nf < 8; nf++) {
      int cl = wn * 64 + nf * 8 + 2 * tig;
      sm_s[cl * 32 + unit]       = ps[nf][0];
      sm_s[(cl + 1) * 32 + unit] = ps[nf][1];
      sm_q[cl * 32 + unit]       = pq[nf][0];
      sm_q[(cl + 1) * 32 + unit] = pq[nf][1];
    }
    __syncthreads();
    if (tid < 128) {
      float s = 0.f, q = 0.f;
#pragma unroll
      for (int u = 0; u < 32; u++) {
        s += sm_s[tid * 32 + u];
        q += sm_q[tid * 32 + u];
      }
      atomicAdd(&g_colsum[tid], s);
      atomicAdd(&g_colsq[tid], q);
    }
  }
}

// ---------------- BatchNorm (+ELU): in-place g_h for l<4, out for l=4 ----------------
__global__ void k_bn(const float* __restrict__ gamma, const float* __restrict__ beta,
                     float* __restrict__ out_ext, int last) {
  int idx = blockIdx.x * 256 + threadIdx.x;  // float4 index
  if (idx >= N_NODES * (EMB / 4)) return;
  int c = (idx & 31) * 4;
  float4 v = *(const float4*)(g_h + (size_t)idx * 4);
  float vv[4] = {v.x, v.y, v.z, v.w};
  float o[4];
  const float inv = 1.f / (float)N_NODES;
#pragma unroll
  for (int j = 0; j < 4; j++) {
    int cc = c + j;
    float mu  = g_colsum[cc] * inv;
    float var = g_colsq[cc] * inv - mu * mu;
    float sc  = rsqrtf(var + 1e-5f) * gamma[cc];
    float xN  = (vv[j] - mu) * sc + beta[cc];
    if (!last) xN = xN > 0.f ? xN : expm1f(xN);
    o[j] = xN;
  }
  float* dst = last ? out_ext : g_h;
  *(float4*)(dst + (size_t)idx * 4) = *(float4*)&o[0];
}

// ---------------- launch ----------------
extern "C" void kernel_launch(void* const* d_in, const int* in_sizes, int n_in,
                              void* d_out, int out_size) {
  const float* x     = (const float*)d_in[0];
  const float* ea    = (const float*)d_in[1];
  const int*   ei    = (const int*)d_in[2];
  const float* Wx    = (const float*)d_in[3];
  const float* bx    = (const float*)d_in[4];
  const float* We    = (const float*)d_in[5];
  const float* be    = (const float*)d_in[6];
  const float* W1    = (const float*)d_in[7];
  const float* b1    = (const float*)d_in[8];
  const float* W2    = (const float*)d_in[9];
  const float* b2    = (const float*)d_in[10];
  const float* gamma = (const float*)d_in[11];
  const float* beta  = (const float*)d_in[12];
  float* out = (float*)d_out;

  cudaFuncSetAttribute(k_fused1, cudaFuncAttributeMaxDynamicSharedMemorySize, F1_SMEM);
  cudaFuncSetAttribute(k_gemm2,  cudaFuncAttributeMaxDynamicSharedMemorySize, G2_SMEM);

  // CSR build (dst-sorted adjacency) + graph preprocessing
  k_zero_cnt<<<CDIV(N_NODES, 256), 256>>>();
  k_hist<<<CDIV(N_EDGES, 256), 256>>>(ei);
  k_scan<<<1, 1024>>>();
  k_fill<<<CDIV(N_EDGES, 256), 256>>>(ei);
  k_prep_graph<<<CDIV(N_NODES, 8), 256>>>(ei, ea);

  // weight transpose + split, initial embedding
  k_prep_w<<<CDIV(2 * 5 * 128 * 256, 256), 256>>>(W1, W2);
  k_init_h<<<N_NODES, EMB>>>(x, Wx, bx);

  const int MT1 = CDIV(N_NODES, 128);  // 391
  const int MT2 = CDIV(N_NODES, 64);   // 782
  for (int l = 0; l < 5; l++) {
    k_fused1<<<MT1, 256, F1_SMEM>>>(l, We + l * EFEAT * EMB, be + l * EFEAT * EMB,
                                    b1 + l * HID);
    k_gemm2<<<MT2, 256, G2_SMEM>>>(l, b2 + l * EMB);
    k_bn<<<CDIV(N_NODES * 32, 256), 256>>>(gamma + l * EMB, beta + l * EMB,
                                           out, (l == 4) ? 1 : 0);
  }
}

// round 13
// speedup vs baseline: 1.0880x; 1.0880x over previous
#include <cuda_runtime.h>
#include <cuda_fp16.h>
#include <math.h>
#include <stdint.h>

#define N_NODES 50000
#define N_EDGES 800000
#define EMB 128
#define NFEAT 7
#define EFEAT 5
#define HID 256
#define CDIV(a,b) (((a)+(b)-1)/(b))

// ---------------- scratch (static device allocations) ----------------
__device__ __align__(16) float  g_h[N_NODES * EMB];      // h (post-BN) / z (post-GEMM2)
__device__ __align__(16) __half g_aggh[N_NODES * EMB];   // agg hi
__device__ __align__(16) __half g_aggl[N_NODES * EMB];   // agg lo
__device__ __align__(16) __half g_th[N_NODES * HID];     // hidden hi
__device__ __align__(16) __half g_tl[N_NODES * HID];     // hidden lo
__device__ __align__(16) __half g_W1h[5 * HID * EMB];    // W1^T hi: [l][n=256][k=128]
__device__ __align__(16) __half g_W1l[5 * HID * EMB];
__device__ __align__(16) __half g_W2h[5 * EMB * HID];    // W2^T hi: [l][n=128][k=256]
__device__ __align__(16) __half g_W2l[5 * EMB * HID];
__device__ int   g_cnt[N_NODES];
__device__ int   g_rowptr[N_NODES + 1];
__device__ int   g_cur[N_NODES];
__device__ int   g_eid[N_EDGES];
__device__ int   g_src[N_EDGES];            // dst-sorted source node ids
__device__ float g_sea[N_NODES * EFEAT];    // per-node sum of edge_attr over in-edges
__device__ float g_colsum[EMB];
__device__ float g_colsq[EMB];

// ---------------- helpers ----------------
__device__ __forceinline__ uint32_t smem_u32(const void* p) {
  uint32_t a;
  asm("{ .reg .u64 t; cvta.to.shared.u64 t, %1; cvt.u32.u64 %0, t; }" : "=r"(a) : "l"(p));
  return a;
}
__device__ __forceinline__ void cp16(uint32_t dst, const void* src, int sz) {
  asm volatile("cp.async.cg.shared.global [%0], [%1], 16, %2;"
               :: "r"(dst), "l"(src), "r"(sz));
}
__device__ __forceinline__ void ldsm4(uint32_t* r, uint32_t addr) {
  asm volatile("ldmatrix.sync.aligned.m8n8.x4.shared.b16 {%0,%1,%2,%3}, [%4];"
               : "=r"(r[0]), "=r"(r[1]), "=r"(r[2]), "=r"(r[3]) : "r"(addr));
}
__device__ __forceinline__ void mma_f16(float* d, const uint32_t* a, const uint32_t* b) {
  asm volatile(
    "mma.sync.aligned.m16n8k16.row.col.f32.f16.f16.f32 "
    "{%0,%1,%2,%3}, {%4,%5,%6,%7}, {%8,%9}, {%0,%1,%2,%3};"
    : "+f"(d[0]), "+f"(d[1]), "+f"(d[2]), "+f"(d[3])
    : "r"(a[0]), "r"(a[1]), "r"(a[2]), "r"(a[3]), "r"(b[0]), "r"(b[1]));
}
__device__ __forceinline__ void split1(float v, __half& h, __half& l) {
  h = __float2half_rn(v);
  l = __float2half_rn(v - __half2float(h));
}

// ---------------- CSR build ----------------
__global__ void k_zero_cnt() {
  int i = blockIdx.x * 256 + threadIdx.x;
  if (i < N_NODES) g_cnt[i] = 0;
}

__global__ void k_hist(const int* __restrict__ ei) {
  int e = blockIdx.x * 256 + threadIdx.x;
  if (e < N_EDGES) atomicAdd(&g_cnt[ei[N_EDGES + e]], 1);
}

__global__ void k_scan() {  // single block, 1024 threads
  __shared__ int sums[1024];
  int t = threadIdx.x;
  const int CH = (N_NODES + 1023) / 1024;
  int base = t * CH;
  int s = 0;
  for (int i = 0; i < CH; i++) {
    int idx = base + i;
    if (idx < N_NODES) s += g_cnt[idx];
  }
  sums[t] = s;
  __syncthreads();
  for (int off = 1; off < 1024; off <<= 1) {
    int v = (t >= off) ? sums[t - off] : 0;
    __syncthreads();
    sums[t] += v;
    __syncthreads();
  }
  int run = (t == 0) ? 0 : sums[t - 1];
  for (int i = 0; i < CH; i++) {
    int idx = base + i;
    if (idx < N_NODES) {
      g_rowptr[idx] = run;
      g_cur[idx]    = run;
      run += g_cnt[idx];
    }
  }
  if (t == 1023) g_rowptr[N_NODES] = run;
}

__global__ void k_fill(const int* __restrict__ ei) {
  int e = blockIdx.x * 256 + threadIdx.x;
  if (e < N_EDGES) {
    int dst = ei[N_EDGES + e];
    int p = atomicAdd(&g_cur[dst], 1);
    g_eid[p] = e;
  }
}

// g_src[p] = src of dst-sorted edge p; g_sea[node] = sum of edge_attr over in-edges.
__global__ __launch_bounds__(256) void k_prep_graph(const int* __restrict__ ei,
                                                    const float* __restrict__ ea) {
  int node = blockIdx.x * 8 + (threadIdx.x >> 5);
  if (node >= N_NODES) return;
  int lane = threadIdx.x & 31;
  int beg = g_rowptr[node], end = g_rowptr[node + 1];
  float s0 = 0.f, s1 = 0.f, s2 = 0.f, s3 = 0.f, s4 = 0.f;
  for (int p = beg + lane; p < end; p += 32) {
    int e = g_eid[p];
    g_src[p] = ei[e];
    const float* a = ea + (size_t)e * EFEAT;
    s0 += a[0]; s1 += a[1]; s2 += a[2]; s3 += a[3]; s4 += a[4];
  }
#pragma unroll
  for (int off = 16; off > 0; off >>= 1) {
    s0 += __shfl_xor_sync(0xffffffffu, s0, off);
    s1 += __shfl_xor_sync(0xffffffffu, s1, off);
    s2 += __shfl_xor_sync(0xffffffffu, s2, off);
    s3 += __shfl_xor_sync(0xffffffffu, s3, off);
    s4 += __shfl_xor_sync(0xffffffffu, s4, off);
  }
  if (lane == 0) {
    float* d = g_sea + (size_t)node * EFEAT;
    d[0] = s0; d[1] = s1; d[2] = s2; d[3] = s3; d[4] = s4;
  }
}

// ---------------- weight transpose + split: W[K,N] -> Wt[N,K] hi/lo ----------------
__global__ void k_prep_w(const float* __restrict__ W1, const float* __restrict__ W2) {
  int idx = blockIdx.x * 256 + threadIdx.x;
  const int T = 5 * 128 * 256;
  if (idx < T) {
    int k = idx & 127, n = (idx >> 7) & 255, l = idx >> 15;
    float v = W1[l * 32768 + k * 256 + n];
    __half h, lo; split1(v, h, lo);
    g_W1h[idx] = h; g_W1l[idx] = lo;
  } else if (idx < 2 * T) {
    int j = idx - T;
    int k = j & 255, n = (j >> 8) & 127, l = j >> 15;
    float v = W2[l * 32768 + k * 128 + n];
    __half h, lo; split1(v, h, lo);
    g_W2h[j] = h; g_W2l[j] = lo;
  }
}

// ---------------- initial node embedding (fp32 h) ----------------
__global__ void k_init_h(const float* __restrict__ x, const float* __restrict__ Wx,
                         const float* __restrict__ bx) {
  __shared__ float xs[NFEAT];
  int i = blockIdx.x;
  int c = threadIdx.x;
  if (c < NFEAT) xs[c] = x[i * NFEAT + c];
  __syncthreads();
  float acc = 0.f;
#pragma unroll
  for (int f = 0; f < NFEAT; f++) acc += xs[f] * Wx[f * EMB + c];
#pragma unroll
  for (int f = 0; f < NFEAT; f++) acc += bx[f * EMB + c];
  g_h[(size_t)i * EMB + c] = acc;
}

// ---------------- gather: agg = h[i] + (deg+1)*sbe + sea[i]@We + sum h[src] ----------------
// Block 0 zeroes BN stats accumulators for this layer (stream-serialized after prior k_bn).
__global__ __launch_bounds__(256) void k_gather(const float* __restrict__ We,
                                                const float* __restrict__ be) {
  __shared__ float sWe[EFEAT][EMB];
  __shared__ float sbe[EMB];
  int t = threadIdx.x;
  if (blockIdx.x == 0 && t < EMB) { g_colsum[t] = 0.f; g_colsq[t] = 0.f; }
  for (int i = t; i < EFEAT * EMB; i += 256) sWe[i / EMB][i % EMB] = We[i];
  if (t < EMB) {
    float s = 0.f;
#pragma unroll
    for (int f = 0; f < EFEAT; f++) s += be[f * EMB + t];
    sbe[t] = s;
  }
  __syncthreads();
  int node = blockIdx.x * 8 + (t >> 5);
  if (node >= N_NODES) return;
  int lane = t & 31;
  int c = lane * 4;

  float4 acc = *(const float4*)(g_h + (size_t)node * EMB + c);
  int beg = g_rowptr[node], end = g_rowptr[node + 1];
  float cnt1 = (float)(end - beg + 1);
  acc.x += cnt1 * sbe[c + 0];
  acc.y += cnt1 * sbe[c + 1];
  acc.z += cnt1 * sbe[c + 2];
  acc.w += cnt1 * sbe[c + 3];

  {  // edge-attr term: sea[node] @ We
    float sv = (lane < EFEAT) ? g_sea[(size_t)node * EFEAT + lane] : 0.f;
    float s0 = __shfl_sync(0xffffffffu, sv, 0);
    float s1 = __shfl_sync(0xffffffffu, sv, 1);
    float s2 = __shfl_sync(0xffffffffu, sv, 2);
    float s3 = __shfl_sync(0xffffffffu, sv, 3);
    float s4 = __shfl_sync(0xffffffffu, sv, 4);
    acc.x += s0*sWe[0][c+0] + s1*sWe[1][c+0] + s2*sWe[2][c+0] + s3*sWe[3][c+0] + s4*sWe[4][c+0];
    acc.y += s0*sWe[0][c+1] + s1*sWe[1][c+1] + s2*sWe[2][c+1] + s3*sWe[3][c+1] + s4*sWe[4][c+1];
    acc.z += s0*sWe[0][c+2] + s1*sWe[1][c+2] + s2*sWe[2][c+2] + s3*sWe[3][c+2] + s4*sWe[4][c+2];
    acc.w += s0*sWe[0][c+3] + s1*sWe[1][c+3] + s2*sWe[2][c+3] + s3*sWe[3][c+3] + s4*sWe[4][c+3];
  }

  int p = beg;
  while (p < end) {
    int nb = min(32, end - p);
    int s_l = (lane < nb) ? g_src[p + lane] : 0;
    int q = 0;
    for (; q + 4 <= nb; q += 4) {
      int s0 = __shfl_sync(0xffffffffu, s_l, q);
      int s1 = __shfl_sync(0xffffffffu, s_l, q + 1);
      int s2 = __shfl_sync(0xffffffffu, s_l, q + 2);
      int s3 = __shfl_sync(0xffffffffu, s_l, q + 3);
      float4 h0 = *(const float4*)(g_h + (size_t)s0 * EMB + c);
      float4 h1 = *(const float4*)(g_h + (size_t)s1 * EMB + c);
      float4 h2 = *(const float4*)(g_h + (size_t)s2 * EMB + c);
      float4 h3 = *(const float4*)(g_h + (size_t)s3 * EMB + c);
      acc.x += (h0.x + h1.x) + (h2.x + h3.x);
      acc.y += (h0.y + h1.y) + (h2.y + h3.y);
      acc.z += (h0.z + h1.z) + (h2.z + h3.z);
      acc.w += (h0.w + h1.w) + (h2.w + h3.w);
    }
    for (; q < nb; q++) {
      int s0 = __shfl_sync(0xffffffffu, s_l, q);
      float4 h0 = *(const float4*)(g_h + (size_t)s0 * EMB + c);
      acc.x += h0.x; acc.y += h0.y; acc.z += h0.z; acc.w += h0.w;
    }
    p += nb;
  }

  __half h0, l0, h1, l1, h2, l2, h3, l3;
  split1(acc.x, h0, l0); split1(acc.y, h1, l1);
  split1(acc.z, h2, l2); split1(acc.w, h3, l3);
  size_t i2 = (size_t)node * (EMB / 2) + (c >> 1);
  ((__half2*)g_aggh)[i2]     = __halves2half2(h0, h1);
  ((__half2*)g_aggh)[i2 + 1] = __halves2half2(h2, h3);
  ((__half2*)g_aggl)[i2]     = __halves2half2(l0, l1);
  ((__half2*)g_aggl)[i2 + 1] = __halves2half2(l2, l3);
}

// ---------------- GEMM1: hidden = relu(agg @ W1^T + b1)  (R7-proven scalar-LDS version) ----------------
// CTA tile 128x128, 8 warps (4m x 2n), K-chunk 32, double-buffered.
__global__ __launch_bounds__(256) void k_gemm1(int layer, const float* __restrict__ bias) {
  extern __shared__ float smf[];
  const __half* Ah = g_aggh;
  const __half* Al = g_aggl;
  const __half* Bh = g_W1h + (size_t)layer * HID * EMB;
  const __half* Bl = g_W1l + (size_t)layer * HID * EMB;
  constexpr int K = 128;

  const int tid  = threadIdx.x;
  const int lane = tid & 31;
  const int warp = tid >> 5;
  const int gid  = lane >> 2;
  const int tig  = lane & 3;
  const int wm   = warp & 3;
  const int wn   = warp >> 2;
  const int brow = blockIdx.x * 128;
  const int bcol = blockIdx.y * 128;

  const uint32_t sbase = smem_u32(smf);
  constexpr int NCH = K / 32;

  float acc[2][8][4];
#pragma unroll
  for (int mf = 0; mf < 2; mf++)
#pragma unroll
    for (int nf = 0; nf < 8; nf++)
#pragma unroll
      for (int j = 0; j < 4; j++) acc[mf][nf][j] = 0.f;

  auto load_chunk = [&](int ck, int b) {
    int k0 = ck * 32;
    uint32_t sbuf = sbase + (uint32_t)b * 32768u;
#pragma unroll
    for (int i = 0; i < 2; i++) {
      int j = tid + i * 256;              // 0..511
      int row = j >> 2, q = j & 3;
      uint32_t doff = (uint32_t)(((q >> 1) << 12) + (row << 5) + ((q & 1) << 4));
      const __half* sa = Ah + (size_t)(brow + row) * K + k0 + q * 8;
      const __half* sl = Al + (size_t)(brow + row) * K + k0 + q * 8;
      int ok = (brow + row < N_NODES) ? 16 : 0;
      cp16(sbuf + doff,          sa, ok);
      cp16(sbuf + 8192u + doff,  sl, ok);
      const __half* bhp = Bh + (size_t)(bcol + row) * K + k0 + q * 8;
      const __half* blp = Bl + (size_t)(bcol + row) * K + k0 + q * 8;
      cp16(sbuf + 16384u + doff, bhp, 16);
      cp16(sbuf + 24576u + doff, blp, 16);
    }
    asm volatile("cp.async.commit_group;");
  };

  load_chunk(0, 0);

  for (int ck = 0; ck < NCH; ck++) {
    int b = ck & 1;
    if (ck + 1 < NCH) {
      load_chunk(ck + 1, b ^ 1);
      asm volatile("cp.async.wait_group 1;");
    } else {
      asm volatile("cp.async.wait_group 0;");
    }
    __syncthreads();

    const uint32_t* pAh = (const uint32_t*)(smf + b * 8192);
    const uint32_t* pAl = pAh + 2048;
    const uint32_t* pBh = pAh + 4096;
    const uint32_t* pBl = pAh + 6144;
#pragma unroll
    for (int kb = 0; kb < 2; kb++) {
      uint32_t ah[2][4], al[2][4];
#pragma unroll
      for (int mf = 0; mf < 2; mf++) {
        int r = wm * 32 + mf * 16 + gid;
        int o0 = kb * 1024 + r * 8;
        int o1 = kb * 1024 + (r + 8) * 8;
        ah[mf][0] = pAh[o0 + tig];     ah[mf][1] = pAh[o1 + tig];
        ah[mf][2] = pAh[o0 + 4 + tig]; ah[mf][3] = pAh[o1 + 4 + tig];
        al[mf][0] = pAl[o0 + tig];     al[mf][1] = pAl[o1 + tig];
        al[mf][2] = pAl[o0 + 4 + tig]; al[mf][3] = pAl[o1 + 4 + tig];
      }
      uint32_t bh[8][2], bl[8][2];
#pragma unroll
      for (int nf = 0; nf < 8; nf++) {
        int n = wn * 64 + nf * 8 + gid;
        int o = kb * 1024 + n * 8;
        bh[nf][0] = pBh[o + tig]; bh[nf][1] = pBh[o + 4 + tig];
        bl[nf][0] = pBl[o + tig]; bl[nf][1] = pBl[o + 4 + tig];
      }
#pragma unroll
      for (int mf = 0; mf < 2; mf++)
#pragma unroll
        for (int nf = 0; nf < 8; nf++) {
          mma_f16(acc[mf][nf], ah[mf], bh[nf]);
          mma_f16(acc[mf][nf], ah[mf], bl[nf]);
          mma_f16(acc[mf][nf], al[mf], bh[nf]);
        }
    }
    __syncthreads();
  }

  // epilogue: bias + relu + hi/lo split -> g_th/g_tl
#pragma unroll
  for (int mf = 0; mf < 2; mf++) {
    int r0 = brow + wm * 32 + mf * 16 + gid;
#pragma unroll
    for (int nf = 0; nf < 8; nf++) {
      int cg = bcol + wn * 64 + nf * 8 + 2 * tig;
      float b0 = bias[cg], b1v = bias[cg + 1];
      float v0 = fmaxf(acc[mf][nf][0] + b0, 0.f);
      float v1 = fmaxf(acc[mf][nf][1] + b1v, 0.f);
      float v2 = fmaxf(acc[mf][nf][2] + b0, 0.f);
      float v3 = fmaxf(acc[mf][nf][3] + b1v, 0.f);
      __half h0, l0, h1, l1;
      if (r0 < N_NODES) {
        split1(v0, h0, l0); split1(v1, h1, l1);
        size_t i2 = (size_t)r0 * (HID / 2) + (cg >> 1);
        ((__half2*)g_th)[i2] = __halves2half2(h0, h1);
        ((__half2*)g_tl)[i2] = __halves2half2(l0, l1);
      }
      if (r0 + 8 < N_NODES) {
        split1(v2, h0, l0); split1(v3, h1, l1);
        size_t i2 = (size_t)(r0 + 8) * (HID / 2) + (cg >> 1);
        ((__half2*)g_th)[i2] = __halves2half2(h0, h1);
        ((__half2*)g_tl)[i2] = __halves2half2(l0, l1);
      }
    }
  }
}

// ---------------- GEMM2: z = hidden @ W2^T + b2, M-tile 64, with BN stats ----------------
// smem per buffer: Ah 4K | Al 4K | Bh 8K | Bl 8K = 24K, x2 buffers = 48K (stats reuse region)
#define G2_SMEM 49152
__global__ __launch_bounds__(256, 2) void k_gemm2(int layer, const float* __restrict__ bias) {
  extern __shared__ float smf[];
  const __half* Ah = g_th;
  const __half* Al = g_tl;
  const __half* Bh = g_W2h + (size_t)layer * EMB * HID;
  const __half* Bl = g_W2l + (size_t)layer * EMB * HID;

  const int tid  = threadIdx.x;
  const int lane = tid & 31;
  const int warp = tid >> 5;
  const int gid  = lane >> 2;
  const int tig  = lane & 3;
  const int wm   = warp & 3;
  const int wn   = warp >> 2;
  const int brow = blockIdx.x * 64;

  const uint32_t sbase = smem_u32(smf);
  constexpr uint32_t AH_SZ = 4096;   // 2 kb x 64 rows x 32B
  constexpr uint32_t BH_SZ = 8192;   // 2 kb x 128 rows x 32B
  constexpr uint32_t BUF   = 2 * AH_SZ + 2 * BH_SZ;  // 24576

  const int rlan = lane & 15;
  const int khl  = lane >> 4;
  uint32_t aoff;
  {
    int row = wm * 16 + rlan;
    aoff = (uint32_t)(row * 32) + (uint32_t)((khl ^ ((row >> 2) & 1)) << 4);
  }
  uint32_t boff[4];
#pragma unroll
  for (int g = 0; g < 4; g++) {
    int n = wn * 64 + g * 16 + rlan;
    boff[g] = (uint32_t)(n * 32) + (uint32_t)((khl ^ ((n >> 2) & 1)) << 4);
  }

  float acc[8][4];
#pragma unroll
  for (int nf = 0; nf < 8; nf++)
#pragma unroll
    for (int j = 0; j < 4; j++) acc[nf][j] = 0.f;

  auto load_chunk = [&](int ck, int b) {
    int k0 = ck * 32;
    uint32_t sbuf = sbase + (uint32_t)b * BUF;
#pragma unroll
    for (int i = 0; i < 3; i++) {
      int j = tid + i * 256;        // 0..767
      if (j < 256) {                // A: 64 rows x 4 q
        int row = j >> 2, q = j & 3;
        int kb = q >> 1, kh = q & 1;
        uint32_t doff = (uint32_t)kb * 2048u + (uint32_t)(row * 32) +
                        (uint32_t)((kh ^ ((row >> 2) & 1)) << 4);
        int ok = (brow + row < N_NODES) ? 16 : 0;
        cp16(sbuf + doff,         Ah + (size_t)(brow + row) * HID + k0 + q * 8, ok);
        cp16(sbuf + AH_SZ + doff, Al + (size_t)(brow + row) * HID + k0 + q * 8, ok);
      } else {                      // B: 128 rows x 4 q
        int jj = j - 256;
        int row = jj >> 2, q = jj & 3;
        int kb = q >> 1, kh = q & 1;
        uint32_t doff = (uint32_t)kb * 4096u + (uint32_t)(row * 32) +
                        (uint32_t)((kh ^ ((row >> 2) & 1)) << 4);
        cp16(sbuf + 2 * AH_SZ + doff,         Bh + (size_t)row * HID + k0 + q * 8, 16);
        cp16(sbuf + 2 * AH_SZ + BH_SZ + doff, Bl + (size_t)row * HID + k0 + q * 8, 16);
      }
    }
    asm volatile("cp.async.commit_group;");
  };

  load_chunk(0, 0);
  for (int ck = 0; ck < 8; ck++) {
    int b = ck & 1;
    if (ck + 1 < 8) {
      load_chunk(ck + 1, b ^ 1);
      asm volatile("cp.async.wait_group 1;");
    } else {
      asm volatile("cp.async.wait_group 0;");
    }
    __syncthreads();
    uint32_t sbuf = sbase + (uint32_t)b * BUF;
#pragma unroll
    for (int kb = 0; kb < 2; kb++) {
      uint32_t ah[4], al[4];
      ldsm4(ah, sbuf + (uint32_t)kb * 2048u + aoff);
      ldsm4(al, sbuf + AH_SZ + (uint32_t)kb * 2048u + aoff);
#pragma unroll
      for (int g = 0; g < 4; g++) {
        uint32_t rh[4], rl[4];
        ldsm4(rh, sbuf + 2 * AH_SZ + (uint32_t)kb * 4096u + boff[g]);
        ldsm4(rl, sbuf + 2 * AH_SZ + BH_SZ + (uint32_t)kb * 4096u + boff[g]);
        uint32_t b0h[2] = {rh[0], rh[2]}, b1h[2] = {rh[1], rh[3]};
        uint32_t b0l[2] = {rl[0], rl[2]}, b1l[2] = {rl[1], rl[3]};
        mma_f16(acc[2 * g],     ah, b0h);
        mma_f16(acc[2 * g],     ah, b0l);
        mma_f16(acc[2 * g],     al, b0h);
        mma_f16(acc[2 * g + 1], ah, b1h);
        mma_f16(acc[2 * g + 1], ah, b1l);
        mma_f16(acc[2 * g + 1], al, b1h);
      }
    }
    __syncthreads();
  }

  // epilogue: bias, write z to g_h, accumulate BN stats
  float ps[8][2], pq[8][2];
#pragma unroll
  for (int nf = 0; nf < 8; nf++) {
    ps[nf][0] = ps[nf][1] = 0.f;
    pq[nf][0] = pq[nf][1] = 0.f;
  }
  int r0 = brow + wm * 16 + gid;
#pragma unroll
  for (int nf = 0; nf < 8; nf++) {
    int cg = wn * 64 + nf * 8 + 2 * tig;
    float b0 = bias[cg], b1v = bias[cg + 1];
    float v0 = acc[nf][0] + b0, v1 = acc[nf][1] + b1v;
    float v2 = acc[nf][2] + b0, v3 = acc[nf][3] + b1v;
    if (r0 < N_NODES) {
      *(float2*)(g_h + (size_t)r0 * EMB + cg) = make_float2(v0, v1);
      ps[nf][0] += v0; pq[nf][0] += v0 * v0;
      ps[nf][1] += v1; pq[nf][1] += v1 * v1;
    }
    if (r0 + 8 < N_NODES) {
      *(float2*)(g_h + (size_t)(r0 + 8) * EMB + cg) = make_float2(v2, v3);
      ps[nf][0] += v2; pq[nf][0] += v2 * v2;
      ps[nf][1] += v3; pq[nf][1] += v3 * v3;
    }
  }
  {
    float* sm_s = smf;                 // [128][32]
    float* sm_q = smf + 128 * 32;      // [128][32]
    __syncthreads();
    int unit = wm * 8 + gid;
#pragma unroll
    for (int nf = 0; nf < 8; nf++) {
      int cl = wn * 64 + nf * 8 + 2 * tig;
      sm_s[cl * 32 + unit]       = ps[nf][0];
      sm_s[(cl + 1) * 32 + unit] = ps[nf][1];
      sm_q[cl * 32 + unit]       = pq[nf][0];
      sm_q[(cl + 1) * 32 + unit] = pq[nf][1];
    }
    __syncthreads();
    if (tid < 128) {
      float s = 0.f, q = 0.f;
#pragma unroll
      for (int u = 0; u < 32; u++) {
        s += sm_s[tid * 32 + u];
        q += sm_q[tid * 32 + u];
      }
      atomicAdd(&g_colsum[tid], s);
      atomicAdd(&g_colsq[tid], q);
    }
  }
}

// ---------------- BatchNorm (+ELU): in-place g_h for l<4, out for l=4 ----------------
__global__ void k_bn(const float* __restrict__ gamma, const float* __restrict__ beta,
                     float* __restrict__ out_ext, int last) {
  int idx = blockIdx.x * 256 + threadIdx.x;  // float4 index
  if (idx >= N_NODES * (EMB / 4)) return;
  int c = (idx & 31) * 4;
  float4 v = *(const float4*)(g_h + (size_t)idx * 4);
  float vv[4] = {v.x, v.y, v.z, v.w};
  float o[4];
  const float inv = 1.f / (float)N_NODES;
#pragma unroll
  for (int j = 0; j < 4; j++) {
    int cc = c + j;
    float mu  = g_colsum[cc] * inv;
    float var = g_colsq[cc] * inv - mu * mu;
    float sc  = rsqrtf(var + 1e-5f) * gamma[cc];
    float xN  = (vv[j] - mu) * sc + beta[cc];
    if (!last) xN = xN > 0.f ? xN : expm1f(xN);
    o[j] = xN;
  }
  float* dst = last ? out_ext : g_h;
  *(float4*)(dst + (size_t)idx * 4) = *(float4*)&o[0];
}

// ---------------- launch ----------------
extern "C" void kernel_launch(void* const* d_in, const int* in_sizes, int n_in,
                              void* d_out, int out_size) {
  const float* x     = (const float*)d_in[0];
  const float* ea    = (const float*)d_in[1];
  const int*   ei    = (const int*)d_in[2];
  const float* Wx    = (const float*)d_in[3];
  const float* bx    = (const float*)d_in[4];
  const float* We    = (const float*)d_in[5];
  const float* be    = (const float*)d_in[6];
  const float* W1    = (const float*)d_in[7];
  const float* b1    = (const float*)d_in[8];
  const float* W2    = (const float*)d_in[9];
  const float* b2    = (const float*)d_in[10];
  const float* gamma = (const float*)d_in[11];
  const float* beta  = (const float*)d_in[12];
  float* out = (float*)d_out;

  const int SMEM1 = 65536;  // 2 buffers x 32KB
  cudaFuncSetAttribute(k_gemm1, cudaFuncAttributeMaxDynamicSharedMemorySize, SMEM1);
  cudaFuncSetAttribute(k_gemm2, cudaFuncAttributeMaxDynamicSharedMemorySize, G2_SMEM);

  // CSR build (dst-sorted adjacency) + graph preprocessing
  k_zero_cnt<<<CDIV(N_NODES, 256), 256>>>();
  k_hist<<<CDIV(N_EDGES, 256), 256>>>(ei);
  k_scan<<<1, 1024>>>();
  k_fill<<<CDIV(N_EDGES, 256), 256>>>(ei);
  k_prep_graph<<<CDIV(N_NODES, 8), 256>>>(ei, ea);

  // weight transpose + split, initial embedding
  k_prep_w<<<CDIV(2 * 5 * 128 * 256, 256), 256>>>(W1, W2);
  k_init_h<<<N_NODES, EMB>>>(x, Wx, bx);

  const int MT1 = CDIV(N_NODES, 128);  // 391
  const int MT2 = CDIV(N_NODES, 64);   // 782
  dim3 g1(MT1, 2);   // 2 x 128 -> 256 cols
  for (int l = 0; l < 5; l++) {
    k_gather<<<CDIV(N_NODES, 8), 256>>>(We + l * EFEAT * EMB, be + l * EFEAT * EMB);
    k_gemm1<<<g1, 256, SMEM1>>>(l, b1 + l * HID);
    k_gemm2<<<MT2, 256, G2_SMEM>>>(l, b2 + l * EMB);
    k_bn<<<CDIV(N_NODES * 32, 256), 256>>>(gamma + l * EMB, beta + l * EMB,
                                           out, (l == 4) ? 1 : 0);
  }
}

// round 15
// speedup vs baseline: 1.1716x; 1.0769x over previous
#include <cuda_runtime.h>
#include <cuda_fp16.h>
#include <math.h>
#include <stdint.h>

#define N_NODES 50000
#define N_EDGES 800000
#define EMB 128
#define NFEAT 7
#define EFEAT 5
#define HID 256
#define CDIV(a,b) (((a)+(b)-1)/(b))

// ---------------- scratch (static device allocations) ----------------
__device__ __align__(16) float  g_h[N_NODES * EMB];      // h (post-BN) / z (post-GEMM2)
__device__ __align__(16) __half g_aggh[N_NODES * EMB];   // agg hi
__device__ __align__(16) __half g_aggl[N_NODES * EMB];   // agg lo
__device__ __align__(16) __half g_th[N_NODES * HID];     // hidden hi
__device__ __align__(16) __half g_tl[N_NODES * HID];     // hidden lo
__device__ __align__(16) __half g_W1h[5 * HID * EMB];    // W1^T hi: [l][n=256][k=128]
__device__ __align__(16) __half g_W1l[5 * HID * EMB];
__device__ __align__(16) __half g_W2h[5 * EMB * HID];    // W2^T hi: [l][n=128][k=256]
__device__ __align__(16) __half g_W2l[5 * EMB * HID];
__device__ int   g_cnt[N_NODES];
__device__ int   g_rowptr[N_NODES + 1];
__device__ int   g_cur[N_NODES];
__device__ int   g_eid[N_EDGES];
__device__ int   g_src[N_EDGES];            // dst-sorted source node ids
__device__ float g_sea[N_NODES * EFEAT];    // per-node sum of edge_attr over in-edges
__device__ float g_colsum[EMB];
__device__ float g_colsq[EMB];

// ---------------- helpers ----------------
__device__ __forceinline__ uint32_t smem_u32(const void* p) {
  uint32_t a;
  asm("{ .reg .u64 t; cvta.to.shared.u64 t, %1; cvt.u32.u64 %0, t; }" : "=r"(a) : "l"(p));
  return a;
}
__device__ __forceinline__ void cp16(uint32_t dst, const void* src, int sz) {
  asm volatile("cp.async.cg.shared.global [%0], [%1], 16, %2;"
               :: "r"(dst), "l"(src), "r"(sz));
}
__device__ __forceinline__ void mma_f16(float* d, const uint32_t* a, const uint32_t* b) {
  asm volatile(
    "mma.sync.aligned.m16n8k16.row.col.f32.f16.f16.f32 "
    "{%0,%1,%2,%3}, {%4,%5,%6,%7}, {%8,%9}, {%0,%1,%2,%3};"
    : "+f"(d[0]), "+f"(d[1]), "+f"(d[2]), "+f"(d[3])
    : "r"(a[0]), "r"(a[1]), "r"(a[2]), "r"(a[3]), "r"(b[0]), "r"(b[1]));
}
__device__ __forceinline__ void split1(float v, __half& h, __half& l) {
  h = __float2half_rn(v);
  l = __float2half_rn(v - __half2float(h));
}

// ---------------- CSR build ----------------
__global__ void k_zero_cnt() {
  int i = blockIdx.x * 256 + threadIdx.x;
  if (i < N_NODES) g_cnt[i] = 0;
}

__global__ void k_hist(const int* __restrict__ ei) {
  int e = blockIdx.x * 256 + threadIdx.x;
  if (e < N_EDGES) atomicAdd(&g_cnt[ei[N_EDGES + e]], 1);
}

__global__ void k_scan() {  // single block, 1024 threads
  __shared__ int sums[1024];
  int t = threadIdx.x;
  const int CH = (N_NODES + 1023) / 1024;
  int base = t * CH;
  int s = 0;
  for (int i = 0; i < CH; i++) {
    int idx = base + i;
    if (idx < N_NODES) s += g_cnt[idx];
  }
  sums[t] = s;
  __syncthreads();
  for (int off = 1; off < 1024; off <<= 1) {
    int v = (t >= off) ? sums[t - off] : 0;
    __syncthreads();
    sums[t] += v;
    __syncthreads();
  }
  int run = (t == 0) ? 0 : sums[t - 1];
  for (int i = 0; i < CH; i++) {
    int idx = base + i;
    if (idx < N_NODES) {
      g_rowptr[idx] = run;
      g_cur[idx]    = run;
      run += g_cnt[idx];
    }
  }
  if (t == 1023) g_rowptr[N_NODES] = run;
}

__global__ void k_fill(const int* __restrict__ ei) {
  int e = blockIdx.x * 256 + threadIdx.x;
  if (e < N_EDGES) {
    int dst = ei[N_EDGES + e];
    int p = atomicAdd(&g_cur[dst], 1);
    g_eid[p] = e;
  }
}

// g_src[p] = src of dst-sorted edge p; g_sea[node] = sum of edge_attr over in-edges.
__global__ __launch_bounds__(256) void k_prep_graph(const int* __restrict__ ei,
                                                    const float* __restrict__ ea) {
  int node = blockIdx.x * 8 + (threadIdx.x >> 5);
  if (node >= N_NODES) return;
  int lane = threadIdx.x & 31;
  int beg = g_rowptr[node], end = g_rowptr[node + 1];
  float s0 = 0.f, s1 = 0.f, s2 = 0.f, s3 = 0.f, s4 = 0.f;
  for (int p = beg + lane; p < end; p += 32) {
    int e = g_eid[p];
    g_src[p] = ei[e];
    const float* a = ea + (size_t)e * EFEAT;
    s0 += a[0]; s1 += a[1]; s2 += a[2]; s3 += a[3]; s4 += a[4];
  }
#pragma unroll
  for (int off = 16; off > 0; off >>= 1) {
    s0 += __shfl_xor_sync(0xffffffffu, s0, off);
    s1 += __shfl_xor_sync(0xffffffffu, s1, off);
    s2 += __shfl_xor_sync(0xffffffffu, s2, off);
    s3 += __shfl_xor_sync(0xffffffffu, s3, off);
    s4 += __shfl_xor_sync(0xffffffffu, s4, off);
  }
  if (lane == 0) {
    float* d = g_sea + (size_t)node * EFEAT;
    d[0] = s0; d[1] = s1; d[2] = s2; d[3] = s3; d[4] = s4;
  }
}

// ---------------- fused: weight transpose+split AND initial node embedding ----------------
// blocks [0, 1280): Wt1/Wt2 hi-lo transpose (2*163840 elems = 1280*256)
// blocks [1280, 26280): init_h, 2 nodes per 256-thread block
__global__ __launch_bounds__(256) void k_prep_wi(const float* __restrict__ W1,
                                                 const float* __restrict__ W2,
                                                 const float* __restrict__ x,
                                                 const float* __restrict__ Wx,
                                                 const float* __restrict__ bx) {
  const int T = 5 * 128 * 256;
  int bid = blockIdx.x;
  int tid = threadIdx.x;
  if (bid < 1280) {
    int idx = bid * 256 + tid;
    if (idx < T) {
      int k = idx & 127, n = (idx >> 7) & 255, l = idx >> 15;
      float v = W1[l * 32768 + k * 256 + n];
      __half h, lo; split1(v, h, lo);
      g_W1h[idx] = h; g_W1l[idx] = lo;
    } else {
      int j = idx - T;
      int k = j & 255, n = (j >> 8) & 127, l = j >> 15;
      float v = W2[l * 32768 + k * 128 + n];
      __half h, lo; split1(v, h, lo);
      g_W2h[j] = h; g_W2l[j] = lo;
    }
  } else {
    __shared__ float xs[2][NFEAT];
    int half = tid >> 7;             // 0 or 1
    int c    = tid & 127;
    int node = (bid - 1280) * 2 + half;
    if (c < NFEAT) xs[half][c] = x[node * NFEAT + c];
    __syncthreads();
    float acc = 0.f;
#pragma unroll
    for (int f = 0; f < NFEAT; f++) acc += xs[half][f] * Wx[f * EMB + c];
#pragma unroll
    for (int f = 0; f < NFEAT; f++) acc += bx[f * EMB + c];
    g_h[(size_t)node * EMB + c] = acc;
  }
}

// ---------------- gather: agg = h[i] + (deg+1)*sbe + sea[i]@We + sum h[src] ----------------
// Block 0 zeroes BN stats accumulators for this layer (stream-serialized after prior k_bn).
__global__ __launch_bounds__(256) void k_gather(const float* __restrict__ We,
                                                const float* __restrict__ be) {
  __shared__ float sWe[EFEAT][EMB];
  __shared__ float sbe[EMB];
  int t = threadIdx.x;
  if (blockIdx.x == 0 && t < EMB) { g_colsum[t] = 0.f; g_colsq[t] = 0.f; }
  for (int i = t; i < EFEAT * EMB; i += 256) sWe[i / EMB][i % EMB] = We[i];
  if (t < EMB) {
    float s = 0.f;
#pragma unroll
    for (int f = 0; f < EFEAT; f++) s += be[f * EMB + t];
    sbe[t] = s;
  }
  __syncthreads();
  int node = blockIdx.x * 8 + (t >> 5);
  if (node >= N_NODES) return;
  int lane = t & 31;
  int c = lane * 4;

  float4 acc = *(const float4*)(g_h + (size_t)node * EMB + c);
  int beg = g_rowptr[node], end = g_rowptr[node + 1];
  float cnt1 = (float)(end - beg + 1);
  acc.x += cnt1 * sbe[c + 0];
  acc.y += cnt1 * sbe[c + 1];
  acc.z += cnt1 * sbe[c + 2];
  acc.w += cnt1 * sbe[c + 3];

  {  // edge-attr term: sea[node] @ We
    float sv = (lane < EFEAT) ? g_sea[(size_t)node * EFEAT + lane] : 0.f;
    float s0 = __shfl_sync(0xffffffffu, sv, 0);
    float s1 = __shfl_sync(0xffffffffu, sv, 1);
    float s2 = __shfl_sync(0xffffffffu, sv, 2);
    float s3 = __shfl_sync(0xffffffffu, sv, 3);
    float s4 = __shfl_sync(0xffffffffu, sv, 4);
    acc.x += s0*sWe[0][c+0] + s1*sWe[1][c+0] + s2*sWe[2][c+0] + s3*sWe[3][c+0] + s4*sWe[4][c+0];
    acc.y += s0*sWe[0][c+1] + s1*sWe[1][c+1] + s2*sWe[2][c+1] + s3*sWe[3][c+1] + s4*sWe[4][c+1];
    acc.z += s0*sWe[0][c+2] + s1*sWe[1][c+2] + s2*sWe[2][c+2] + s3*sWe[3][c+2] + s4*sWe[4][c+2];
    acc.w += s0*sWe[0][c+3] + s1*sWe[1][c+3] + s2*sWe[2][c+3] + s3*sWe[3][c+3] + s4*sWe[4][c+3];
  }

  int p = beg;
  while (p < end) {
    int nb = min(32, end - p);
    int s_l = (lane < nb) ? g_src[p + lane] : 0;
    int q = 0;
    for (; q + 4 <= nb; q += 4) {
      int s0 = __shfl_sync(0xffffffffu, s_l, q);
      int s1 = __shfl_sync(0xffffffffu, s_l, q + 1);
      int s2 = __shfl_sync(0xffffffffu, s_l, q + 2);
      int s3 = __shfl_sync(0xffffffffu, s_l, q + 3);
      float4 h0 = *(const float4*)(g_h + (size_t)s0 * EMB + c);
      float4 h1 = *(const float4*)(g_h + (size_t)s1 * EMB + c);
      float4 h2 = *(const float4*)(g_h + (size_t)s2 * EMB + c);
      float4 h3 = *(const float4*)(g_h + (size_t)s3 * EMB + c);
      acc.x += (h0.x + h1.x) + (h2.x + h3.x);
      acc.y += (h0.y + h1.y) + (h2.y + h3.y);
      acc.z += (h0.z + h1.z) + (h2.z + h3.z);
      acc.w += (h0.w + h1.w) + (h2.w + h3.w);
    }
    for (; q < nb; q++) {
      int s0 = __shfl_sync(0xffffffffu, s_l, q);
      float4 h0 = *(const float4*)(g_h + (size_t)s0 * EMB + c);
      acc.x += h0.x; acc.y += h0.y; acc.z += h0.z; acc.w += h0.w;
    }
    p += nb;
  }

  __half h0, l0, h1, l1, h2, l2, h3, l3;
  split1(acc.x, h0, l0); split1(acc.y, h1, l1);
  split1(acc.z, h2, l2); split1(acc.w, h3, l3);
  size_t i2 = (size_t)node * (EMB / 2) + (c >> 1);
  ((__half2*)g_aggh)[i2]     = __halves2half2(h0, h1);
  ((__half2*)g_aggh)[i2 + 1] = __halves2half2(h2, h3);
  ((__half2*)g_aggl)[i2]     = __halves2half2(l0, l1);
  ((__half2*)g_aggl)[i2 + 1] = __halves2half2(l2, l3);
}

// ---------------- fp16-split mma GEMM (R7-measured scalar-LDS version) ----------------
// C = act(A @ Wt^T + bias); CTA tile 128x128, 8 warps (4m x 2n), K-chunk 32, double-buffered.
// STATS: accumulate column sum/sumsq of outputs into g_colsum/g_colsq (for BN).
template<int K, int NC, bool RELU, bool SPLIT_OUT, bool SRC_AGG, bool STATS>
__global__ __launch_bounds__(256) void k_gemm_mma(int layer, const float* __restrict__ bias) {
  extern __shared__ float smf[];
  const __half* Ah = SRC_AGG ? g_aggh : g_th;
  const __half* Al = SRC_AGG ? g_aggl : g_tl;
  const __half* Bh = SRC_AGG ? (g_W1h + (size_t)layer * HID * EMB)
                             : (g_W2h + (size_t)layer * EMB * HID);
  const __half* Bl = SRC_AGG ? (g_W1l + (size_t)layer * HID * EMB)
                             : (g_W2l + (size_t)layer * EMB * HID);

  const int tid  = threadIdx.x;
  const int lane = tid & 31;
  const int warp = tid >> 5;
  const int gid  = lane >> 2;
  const int tig  = lane & 3;
  const int wm   = warp & 3;
  const int wn   = warp >> 2;
  const int brow = blockIdx.x * 128;
  const int bcol = blockIdx.y * 128;

  const uint32_t sbase = smem_u32(smf);
  constexpr int NCH = K / 32;

  float acc[2][8][4];
#pragma unroll
  for (int mf = 0; mf < 2; mf++)
#pragma unroll
    for (int nf = 0; nf < 8; nf++)
#pragma unroll
      for (int j = 0; j < 4; j++) acc[mf][nf][j] = 0.f;

  auto load_chunk = [&](int ck, int b) {
    int k0 = ck * 32;
    uint32_t sbuf = sbase + (uint32_t)b * 32768u;
#pragma unroll
    for (int i = 0; i < 2; i++) {
      int j = tid + i * 256;              // 0..511
      int row = j >> 2, q = j & 3;
      uint32_t doff = (uint32_t)(((q >> 1) << 12) + (row << 5) + ((q & 1) << 4));
      const __half* sa = Ah + (size_t)(brow + row) * K + k0 + q * 8;
      const __half* sl = Al + (size_t)(brow + row) * K + k0 + q * 8;
      int ok = (brow + row < N_NODES) ? 16 : 0;
      cp16(sbuf + doff,          sa, ok);
      cp16(sbuf + 8192u + doff,  sl, ok);
      const __half* bhp = Bh + (size_t)(bcol + row) * K + k0 + q * 8;
      const __half* blp = Bl + (size_t)(bcol + row) * K + k0 + q * 8;
      cp16(sbuf + 16384u + doff, bhp, 16);
      cp16(sbuf + 24576u + doff, blp, 16);
    }
    asm volatile("cp.async.commit_group;");
  };

  load_chunk(0, 0);

  for (int ck = 0; ck < NCH; ck++) {
    int b = ck & 1;
    if (ck + 1 < NCH) {
      load_chunk(ck + 1, b ^ 1);
      asm volatile("cp.async.wait_group 1;");
    } else {
      asm volatile("cp.async.wait_group 0;");
    }
    __syncthreads();

    const uint32_t* pAh = (const uint32_t*)(smf + b * 8192);
    const uint32_t* pAl = pAh + 2048;
    const uint32_t* pBh = pAh + 4096;
    const uint32_t* pBl = pAh + 6144;
#pragma unroll
    for (int kb = 0; kb < 2; kb++) {
      uint32_t ah[2][4], al[2][4];
#pragma unroll
      for (int mf = 0; mf < 2; mf++) {
        int r = wm * 32 + mf * 16 + gid;
        int o0 = kb * 1024 + r * 8;
        int o1 = kb * 1024 + (r + 8) * 8;
        ah[mf][0] = pAh[o0 + tig];     ah[mf][1] = pAh[o1 + tig];
        ah[mf][2] = pAh[o0 + 4 + tig]; ah[mf][3] = pAh[o1 + 4 + tig];
        al[mf][0] = pAl[o0 + tig];     al[mf][1] = pAl[o1 + tig];
        al[mf][2] = pAl[o0 + 4 + tig]; al[mf][3] = pAl[o1 + 4 + tig];
      }
      uint32_t bh[8][2], bl[8][2];
#pragma unroll
      for (int nf = 0; nf < 8; nf++) {
        int n = wn * 64 + nf * 8 + gid;
        int o = kb * 1024 + n * 8;
        bh[nf][0] = pBh[o + tig]; bh[nf][1] = pBh[o + 4 + tig];
        bl[nf][0] = pBl[o + tig]; bl[nf][1] = pBl[o + 4 + tig];
      }
#pragma unroll
      for (int mf = 0; mf < 2; mf++)
#pragma unroll
        for (int nf = 0; nf < 8; nf++) {
          mma_f16(acc[mf][nf], ah[mf], bh[nf]);
          mma_f16(acc[mf][nf], ah[mf], bl[nf]);
          mma_f16(acc[mf][nf], al[mf], bh[nf]);
        }
    }
    __syncthreads();
  }

  // ---- epilogue ----
  float ps[8][2], pq[8][2];
  if (STATS) {
#pragma unroll
    for (int nf = 0; nf < 8; nf++) {
      ps[nf][0] = ps[nf][1] = 0.f;
      pq[nf][0] = pq[nf][1] = 0.f;
    }
  }
#pragma unroll
  for (int mf = 0; mf < 2; mf++) {
    int r0 = brow + wm * 32 + mf * 16 + gid;
#pragma unroll
    for (int nf = 0; nf < 8; nf++) {
      int cg = bcol + wn * 64 + nf * 8 + 2 * tig;
      float b0 = bias[cg], b1 = bias[cg + 1];
      float v0 = acc[mf][nf][0] + b0, v1 = acc[mf][nf][1] + b1;
      float v2 = acc[mf][nf][2] + b0, v3 = acc[mf][nf][3] + b1;
      if (RELU) {
        v0 = fmaxf(v0, 0.f); v1 = fmaxf(v1, 0.f);
        v2 = fmaxf(v2, 0.f); v3 = fmaxf(v3, 0.f);
      }
      if (SPLIT_OUT) {
        __half h0, l0, h1, l1;
        if (r0 < N_NODES) {
          split1(v0, h0, l0); split1(v1, h1, l1);
          size_t i2 = (size_t)r0 * (NC / 2) + (cg >> 1);
          ((__half2*)g_th)[i2] = __halves2half2(h0, h1);
          ((__half2*)g_tl)[i2] = __halves2half2(l0, l1);
        }
        if (r0 + 8 < N_NODES) {
          split1(v2, h0, l0); split1(v3, h1, l1);
          size_t i2 = (size_t)(r0 + 8) * (NC / 2) + (cg >> 1);
          ((__half2*)g_th)[i2] = __halves2half2(h0, h1);
          ((__half2*)g_tl)[i2] = __halves2half2(l0, l1);
        }
      } else {
        if (r0 < N_NODES) *(float2*)(g_h + (size_t)r0 * NC + cg) = make_float2(v0, v1);
        if (r0 + 8 < N_NODES) *(float2*)(g_h + (size_t)(r0 + 8) * NC + cg) = make_float2(v2, v3);
      }
      if (STATS) {
        if (r0 < N_NODES) {
          ps[nf][0] += v0; pq[nf][0] += v0 * v0;
          ps[nf][1] += v1; pq[nf][1] += v1 * v1;
        }
        if (r0 + 8 < N_NODES) {
          ps[nf][0] += v2; pq[nf][0] += v2 * v2;
          ps[nf][1] += v3; pq[nf][1] += v3 * v3;
        }
      }
    }
  }

  if (STATS) {
    float* sm_s = smf;                    // [NC][32]
    float* sm_q = smf + NC * 32;          // [NC][32]
    __syncthreads();
    int unit = wm * 8 + gid;
#pragma unroll
    for (int nf = 0; nf < 8; nf++) {
      int cl = wn * 64 + nf * 8 + 2 * tig;
      sm_s[cl * 32 + unit]       = ps[nf][0];
      sm_s[(cl + 1) * 32 + unit] = ps[nf][1];
      sm_q[cl * 32 + unit]       = pq[nf][0];
      sm_q[(cl + 1) * 32 + unit] = pq[nf][1];
    }
    __syncthreads();
    if (tid < NC) {
      float s = 0.f, q = 0.f;
#pragma unroll
      for (int u = 0; u < 32; u++) {
        s += sm_s[tid * 32 + u];
        q += sm_q[tid * 32 + u];
      }
      atomicAdd(&g_colsum[bcol + tid], s);
      atomicAdd(&g_colsq[bcol + tid], q);
    }
  }
}

// ---------------- BatchNorm (+ELU): in-place g_h for l<4, out for l=4 ----------------
__global__ void k_bn(const float* __restrict__ gamma, const float* __restrict__ beta,
                     float* __restrict__ out_ext, int last) {
  int idx = blockIdx.x * 256 + threadIdx.x;  // float4 index
  if (idx >= N_NODES * (EMB / 4)) return;
  int c = (idx & 31) * 4;
  float4 v = *(const float4*)(g_h + (size_t)idx * 4);
  float vv[4] = {v.x, v.y, v.z, v.w};
  float o[4];
  const float inv = 1.f / (float)N_NODES;
#pragma unroll
  for (int j = 0; j < 4; j++) {
    int cc = c + j;
    float mu  = g_colsum[cc] * inv;
    float var = g_colsq[cc] * inv - mu * mu;
    float sc  = rsqrtf(var + 1e-5f) * gamma[cc];
    float xN  = (vv[j] - mu) * sc + beta[cc];
    if (!last) xN = xN > 0.f ? xN : expm1f(xN);
    o[j] = xN;
  }
  float* dst = last ? out_ext : g_h;
  *(float4*)(dst + (size_t)idx * 4) = *(float4*)&o[0];
}

// ---------------- launch ----------------
extern "C" void kernel_launch(void* const* d_in, const int* in_sizes, int n_in,
                              void* d_out, int out_size) {
  const float* x     = (const float*)d_in[0];
  const float* ea    = (const float*)d_in[1];
  const int*   ei    = (const int*)d_in[2];
  const float* Wx    = (const float*)d_in[3];
  const float* bx    = (const float*)d_in[4];
  const float* We    = (const float*)d_in[5];
  const float* be    = (const float*)d_in[6];
  const float* W1    = (const float*)d_in[7];
  const float* b1    = (const float*)d_in[8];
  const float* W2    = (const float*)d_in[9];
  const float* b2    = (const float*)d_in[10];
  const float* gamma = (const float*)d_in[11];
  const float* beta  = (const float*)d_in[12];
  float* out = (float*)d_out;

  const int SMEM = 65536;  // 2 buffers x 32KB
  static cudaStream_t s2;
  static cudaEvent_t  evA, evB;
  static int once = 0;
  if (!once) {
    cudaFuncSetAttribute(k_gemm_mma<128, 256, true,  true,  true,  false>,
                         cudaFuncAttributeMaxDynamicSharedMemorySize, SMEM);
    cudaFuncSetAttribute(k_gemm_mma<256, 128, false, false, false, true>,
                         cudaFuncAttributeMaxDynamicSharedMemorySize, SMEM);
    cudaStreamCreateWithFlags(&s2, cudaStreamNonBlocking);
    cudaEventCreateWithFlags(&evA, cudaEventDisableTiming);
    cudaEventCreateWithFlags(&evB, cudaEventDisableTiming);
    once = 1;
  }

  // ---- fork: weight-split + initial embedding on s2, CSR chain on main stream ----
  cudaEventRecord(evA, 0);
  cudaStreamWaitEvent(s2, evA, 0);
  k_prep_wi<<<1280 + 25000, 256, 0, s2>>>(W1, W2, x, Wx, bx);
  cudaEventRecord(evB, s2);

  k_zero_cnt<<<CDIV(N_NODES, 256), 256>>>();
  k_hist<<<CDIV(N_EDGES, 256), 256>>>(ei);
  k_scan<<<1, 1024>>>();
  k_fill<<<CDIV(N_EDGES, 256), 256>>>(ei);
  k_prep_graph<<<CDIV(N_NODES, 8), 256>>>(ei, ea);

  cudaStreamWaitEvent(0, evB, 0);   // join before the layer loop

  const int MT = CDIV(N_NODES, 128);  // 391
  dim3 g1(MT, 2);   // 2 x 128 -> 256 cols
  dim3 g2(MT, 1);   // 128 cols
  for (int l = 0; l < 5; l++) {
    k_gather<<<CDIV(N_NODES, 8), 256>>>(We + l * EFEAT * EMB, be + l * EFEAT * EMB);
    k_gemm_mma<128, 256, true,  true,  true,  false><<<g1, 256, SMEM>>>(l, b1 + l * HID);
    k_gemm_mma<256, 128, false, false, false, true ><<<g2, 256, SMEM>>>(l, b2 + l * EMB);
    k_bn<<<CDIV(N_NODES * 32, 256), 256>>>(gamma + l * EMB, beta + l * EMB,
                                           out, (l == 4) ? 1 : 0);
  }
}

// round 17
// speedup vs baseline: 1.2622x; 1.0773x over previous
#include <cuda_runtime.h>
#include <cuda_fp16.h>
#include <math.h>
#include <stdint.h>

#define N_NODES 50000
#define N_EDGES 800000
#define EMB 128
#define NFEAT 7
#define EFEAT 5
#define HID 256
#define CDIV(a,b) (((a)+(b)-1)/(b))
#define SCAN_BLKS 49   // CDIV(N_NODES, 1024)

// ---------------- scratch (static device allocations) ----------------
__device__ __align__(16) float  g_h[N_NODES * EMB];      // h (post-BN) / z (post-GEMM2)
__device__ __align__(16) __half g_aggh[N_NODES * EMB];   // agg hi
__device__ __align__(16) __half g_aggl[N_NODES * EMB];   // agg lo
__device__ __align__(16) __half g_th[N_NODES * HID];     // hidden hi
__device__ __align__(16) __half g_tl[N_NODES * HID];     // hidden lo
__device__ __align__(16) __half g_W1h[5 * HID * EMB];    // W1^T hi: [l][n=256][k=128]
__device__ __align__(16) __half g_W1l[5 * HID * EMB];
__device__ __align__(16) __half g_W2h[5 * EMB * HID];    // W2^T hi: [l][n=128][k=256]
__device__ __align__(16) __half g_W2l[5 * EMB * HID];
__device__ int   g_cnt[N_NODES];
__device__ int   g_rowptr[N_NODES + 1];
__device__ int   g_cur[N_NODES];
__device__ int   g_eid[N_EDGES];
__device__ int   g_src[N_EDGES];            // dst-sorted source node ids
__device__ int   g_part[SCAN_BLKS];
__device__ int   g_poff[SCAN_BLKS];
__device__ float g_sea[N_NODES * EFEAT];    // per-node sum of edge_attr over in-edges
__device__ float g_colsum[EMB];
__device__ float g_colsq[EMB];

// ---------------- helpers ----------------
__device__ __forceinline__ uint32_t smem_u32(const void* p) {
  uint32_t a;
  asm("{ .reg .u64 t; cvta.to.shared.u64 t, %1; cvt.u32.u64 %0, t; }" : "=r"(a) : "l"(p));
  return a;
}
__device__ __forceinline__ void cp16(uint32_t dst, const void* src, int sz) {
  asm volatile("cp.async.cg.shared.global [%0], [%1], 16, %2;"
               :: "r"(dst), "l"(src), "r"(sz));
}
__device__ __forceinline__ void mma_f16(float* d, const uint32_t* a, const uint32_t* b) {
  asm volatile(
    "mma.sync.aligned.m16n8k16.row.col.f32.f16.f16.f32 "
    "{%0,%1,%2,%3}, {%4,%5,%6,%7}, {%8,%9}, {%0,%1,%2,%3};"
    : "+f"(d[0]), "+f"(d[1]), "+f"(d[2]), "+f"(d[3])
    : "r"(a[0]), "r"(a[1]), "r"(a[2]), "r"(a[3]), "r"(b[0]), "r"(b[1]));
}
__device__ __forceinline__ void split1(float v, __half& h, __half& l) {
  h = __float2half_rn(v);
  l = __float2half_rn(v - __half2float(h));
}

// ---------------- CSR build ----------------
__global__ void k_zero_cnt() {
  int i = blockIdx.x * 256 + threadIdx.x;
  if (i < N_NODES) g_cnt[i] = 0;
}

__global__ void k_hist(const int* __restrict__ ei) {
  int e = blockIdx.x * 256 + threadIdx.x;
  if (e < N_EDGES) atomicAdd(&g_cnt[ei[N_EDGES + e]], 1);
}

// 3-pass parallel prefix scan of g_cnt -> g_rowptr (exclusive), g_cur
__global__ void k_scan1() {  // SCAN_BLKS x 1024
  __shared__ int sh[1024];
  int t = threadIdx.x;
  int gid = blockIdx.x * 1024 + t;
  int v = (gid < N_NODES) ? g_cnt[gid] : 0;
  sh[t] = v;
  __syncthreads();
#pragma unroll
  for (int off = 1; off < 1024; off <<= 1) {
    int u = (t >= off) ? sh[t - off] : 0;
    __syncthreads();
    sh[t] += u;
    __syncthreads();
  }
  if (gid < N_NODES) g_rowptr[gid] = sh[t] - v;   // exclusive, block-local
  if (t == 1023) g_part[blockIdx.x] = sh[1023];
}

__global__ void k_scan2() {  // 1 block, 32 threads (thread 0 serial over 49 partials)
  if (threadIdx.x == 0) {
    int run = 0;
#pragma unroll
    for (int i = 0; i < SCAN_BLKS; i++) {
      int c = g_part[i];
      g_poff[i] = run;
      run += c;
    }
    g_rowptr[N_NODES] = run;
  }
}

__global__ void k_scan3() {  // SCAN_BLKS x 1024
  int gid = blockIdx.x * 1024 + threadIdx.x;
  if (gid < N_NODES) {
    int r = g_rowptr[gid] + g_poff[blockIdx.x];
    g_rowptr[gid] = r;
    g_cur[gid] = r;
  }
}

__global__ void k_fill(const int* __restrict__ ei) {
  int e = blockIdx.x * 256 + threadIdx.x;
  if (e < N_EDGES) {
    int dst = ei[N_EDGES + e];
    int p = atomicAdd(&g_cur[dst], 1);
    g_eid[p] = e;
  }
}

// g_src[p] = src of dst-sorted edge p; g_sea[node] = sum of edge_attr over in-edges.
__global__ __launch_bounds__(256) void k_prep_graph(const int* __restrict__ ei,
                                                    const float* __restrict__ ea) {
  int node = blockIdx.x * 8 + (threadIdx.x >> 5);
  if (node >= N_NODES) return;
  int lane = threadIdx.x & 31;
  int beg = g_rowptr[node], end = g_rowptr[node + 1];
  float s0 = 0.f, s1 = 0.f, s2 = 0.f, s3 = 0.f, s4 = 0.f;
  for (int p = beg + lane; p < end; p += 32) {
    int e = g_eid[p];
    g_src[p] = ei[e];
    const float* a = ea + (size_t)e * EFEAT;
    s0 += a[0]; s1 += a[1]; s2 += a[2]; s3 += a[3]; s4 += a[4];
  }
#pragma unroll
  for (int off = 16; off > 0; off >>= 1) {
    s0 += __shfl_xor_sync(0xffffffffu, s0, off);
    s1 += __shfl_xor_sync(0xffffffffu, s1, off);
    s2 += __shfl_xor_sync(0xffffffffu, s2, off);
    s3 += __shfl_xor_sync(0xffffffffu, s3, off);
    s4 += __shfl_xor_sync(0xffffffffu, s4, off);
  }
  if (lane == 0) {
    float* d = g_sea + (size_t)node * EFEAT;
    d[0] = s0; d[1] = s1; d[2] = s2; d[3] = s3; d[4] = s4;
  }
}

// ---------------- fused: weight transpose+split AND initial node embedding ----------------
// blocks [0, 1280): Wt1/Wt2 hi-lo transpose (2*163840 elems = 1280*256)
// blocks [1280, 26280): init_h, 2 nodes per 256-thread block
__global__ __launch_bounds__(256) void k_prep_wi(const float* __restrict__ W1,
                                                 const float* __restrict__ W2,
                                                 const float* __restrict__ x,
                                                 const float* __restrict__ Wx,
                                                 const float* __restrict__ bx) {
  const int T = 5 * 128 * 256;
  int bid = blockIdx.x;
  int tid = threadIdx.x;
  if (bid < 1280) {
    int idx = bid * 256 + tid;
    if (idx < T) {
      int k = idx & 127, n = (idx >> 7) & 255, l = idx >> 15;
      float v = W1[l * 32768 + k * 256 + n];
      __half h, lo; split1(v, h, lo);
      g_W1h[idx] = h; g_W1l[idx] = lo;
    } else {
      int j = idx - T;
      int k = j & 255, n = (j >> 8) & 127, l = j >> 15;
      float v = W2[l * 32768 + k * 128 + n];
      __half h, lo; split1(v, h, lo);
      g_W2h[j] = h; g_W2l[j] = lo;
    }
  } else {
    __shared__ float xs[2][NFEAT];
    int half = tid >> 7;             // 0 or 1
    int c    = tid & 127;
    int node = (bid - 1280) * 2 + half;
    if (c < NFEAT) xs[half][c] = x[node * NFEAT + c];
    __syncthreads();
    float acc = 0.f;
#pragma unroll
    for (int f = 0; f < NFEAT; f++) acc += xs[half][f] * Wx[f * EMB + c];
#pragma unroll
    for (int f = 0; f < NFEAT; f++) acc += bx[f * EMB + c];
    g_h[(size_t)node * EMB + c] = acc;
  }
}

// ---------------- gather: agg = h[i] + (deg+1)*sbe + sea[i]@We + sum h[src] ----------------
// Block 0 zeroes BN stats accumulators for this layer (stream-serialized after prior k_bn).
__global__ __launch_bounds__(256) void k_gather(const float* __restrict__ We,
                                                const float* __restrict__ be) {
  __shared__ float sWe[EFEAT][EMB];
  __shared__ float sbe[EMB];
  int t = threadIdx.x;
  if (blockIdx.x == 0 && t < EMB) { g_colsum[t] = 0.f; g_colsq[t] = 0.f; }
  for (int i = t; i < EFEAT * EMB; i += 256) sWe[i / EMB][i % EMB] = We[i];
  if (t < EMB) {
    float s = 0.f;
#pragma unroll
    for (int f = 0; f < EFEAT; f++) s += be[f * EMB + t];
    sbe[t] = s;
  }
  __syncthreads();
  int node = blockIdx.x * 8 + (t >> 5);
  if (node >= N_NODES) return;
  int lane = t & 31;
  int c = lane * 4;

  float4 acc = *(const float4*)(g_h + (size_t)node * EMB + c);
  int beg = g_rowptr[node], end = g_rowptr[node + 1];
  float cnt1 = (float)(end - beg + 1);
  acc.x += cnt1 * sbe[c + 0];
  acc.y += cnt1 * sbe[c + 1];
  acc.z += cnt1 * sbe[c + 2];
  acc.w += cnt1 * sbe[c + 3];

  {  // edge-attr term: sea[node] @ We
    float sv = (lane < EFEAT) ? g_sea[(size_t)node * EFEAT + lane] : 0.f;
    float s0 = __shfl_sync(0xffffffffu, sv, 0);
    float s1 = __shfl_sync(0xffffffffu, sv, 1);
    float s2 = __shfl_sync(0xffffffffu, sv, 2);
    float s3 = __shfl_sync(0xffffffffu, sv, 3);
    float s4 = __shfl_sync(0xffffffffu, sv, 4);
    acc.x += s0*sWe[0][c+0] + s1*sWe[1][c+0] + s2*sWe[2][c+0] + s3*sWe[3][c+0] + s4*sWe[4][c+0];
    acc.y += s0*sWe[0][c+1] + s1*sWe[1][c+1] + s2*sWe[2][c+1] + s3*sWe[3][c+1] + s4*sWe[4][c+1];
    acc.z += s0*sWe[0][c+2] + s1*sWe[1][c+2] + s2*sWe[2][c+2] + s3*sWe[3][c+2] + s4*sWe[4][c+2];
    acc.w += s0*sWe[0][c+3] + s1*sWe[1][c+3] + s2*sWe[2][c+3] + s3*sWe[3][c+3] + s4*sWe[4][c+3];
  }

  int p = beg;
  while (p < end) {
    int nb = min(32, end - p);
    int s_l = (lane < nb) ? g_src[p + lane] : 0;
    int q = 0;
    for (; q + 4 <= nb; q += 4) {
      int s0 = __shfl_sync(0xffffffffu, s_l, q);
      int s1 = __shfl_sync(0xffffffffu, s_l, q + 1);
      int s2 = __shfl_sync(0xffffffffu, s_l, q + 2);
      int s3 = __shfl_sync(0xffffffffu, s_l, q + 3);
      float4 h0 = *(const float4*)(g_h + (size_t)s0 * EMB + c);
      float4 h1 = *(const float4*)(g_h + (size_t)s1 * EMB + c);
      float4 h2 = *(const float4*)(g_h + (size_t)s2 * EMB + c);
      float4 h3 = *(const float4*)(g_h + (size_t)s3 * EMB + c);
      acc.x += (h0.x + h1.x) + (h2.x + h3.x);
      acc.y += (h0.y + h1.y) + (h2.y + h3.y);
      acc.z += (h0.z + h1.z) + (h2.z + h3.z);
      acc.w += (h0.w + h1.w) + (h2.w + h3.w);
    }
    for (; q < nb; q++) {
      int s0 = __shfl_sync(0xffffffffu, s_l, q);
      float4 h0 = *(const float4*)(g_h + (size_t)s0 * EMB + c);
      acc.x += h0.x; acc.y += h0.y; acc.z += h0.z; acc.w += h0.w;
    }
    p += nb;
  }

  __half h0, l0, h1, l1, h2, l2, h3, l3;
  split1(acc.x, h0, l0); split1(acc.y, h1, l1);
  split1(acc.z, h2, l2); split1(acc.w, h3, l3);
  size_t i2 = (size_t)node * (EMB / 2) + (c >> 1);
  ((__half2*)g_aggh)[i2]     = __halves2half2(h0, h1);
  ((__half2*)g_aggh)[i2 + 1] = __halves2half2(h2, h3);
  ((__half2*)g_aggl)[i2]     = __halves2half2(l0, l1);
  ((__half2*)g_aggl)[i2 + 1] = __halves2half2(l2, l3);
}

// ---------------- fp16-split mma GEMM (R7-measured scalar-LDS version) ----------------
// C = act(A @ Wt^T + bias); CTA tile 128x128, 8 warps (4m x 2n), K-chunk 32, double-buffered.
// STATS: accumulate column sum/sumsq of outputs into g_colsum/g_colsq (for BN).
template<int K, int NC, bool RELU, bool SPLIT_OUT, bool SRC_AGG, bool STATS>
__global__ __launch_bounds__(256) void k_gemm_mma(int layer, const float* __restrict__ bias) {
  extern __shared__ float smf[];
  const __half* Ah = SRC_AGG ? g_aggh : g_th;
  const __half* Al = SRC_AGG ? g_aggl : g_tl;
  const __half* Bh = SRC_AGG ? (g_W1h + (size_t)layer * HID * EMB)
                             : (g_W2h + (size_t)layer * EMB * HID);
  const __half* Bl = SRC_AGG ? (g_W1l + (size_t)layer * HID * EMB)
                             : (g_W2l + (size_t)layer * EMB * HID);

  const int tid  = threadIdx.x;
  const int lane = tid & 31;
  const int warp = tid >> 5;
  const int gid  = lane >> 2;
  const int tig  = lane & 3;
  const int wm   = warp & 3;
  const int wn   = warp >> 2;
  const int brow = blockIdx.x * 128;
  const int bcol = blockIdx.y * 128;

  const uint32_t sbase = smem_u32(smf);
  constexpr int NCH = K / 32;

  float acc[2][8][4];
#pragma unroll
  for (int mf = 0; mf < 2; mf++)
#pragma unroll
    for (int nf = 0; nf < 8; nf++)
#pragma unroll
      for (int j = 0; j < 4; j++) acc[mf][nf][j] = 0.f;

  auto load_chunk = [&](int ck, int b) {
    int k0 = ck * 32;
    uint32_t sbuf = sbase + (uint32_t)b * 32768u;
#pragma unroll
    for (int i = 0; i < 2; i++) {
      int j = tid + i * 256;              // 0..511
      int row = j >> 2, q = j & 3;
      uint32_t doff = (uint32_t)(((q >> 1) << 12) + (row << 5) + ((q & 1) << 4));
      const __half* sa = Ah + (size_t)(brow + row) * K + k0 + q * 8;
      const __half* sl = Al + (size_t)(brow + row) * K + k0 + q * 8;
      int ok = (brow + row < N_NODES) ? 16 : 0;
      cp16(sbuf + doff,          sa, ok);
      cp16(sbuf + 8192u + doff,  sl, ok);
      const __half* bhp = Bh + (size_t)(bcol + row) * K + k0 + q * 8;
      const __half* blp = Bl + (size_t)(bcol + row) * K + k0 + q * 8;
      cp16(sbuf + 16384u + doff, bhp, 16);
      cp16(sbuf + 24576u + doff, blp, 16);
    }
    asm volatile("cp.async.commit_group;");
  };

  load_chunk(0, 0);

  for (int ck = 0; ck < NCH; ck++) {
    int b = ck & 1;
    if (ck + 1 < NCH) {
      load_chunk(ck + 1, b ^ 1);
      asm volatile("cp.async.wait_group 1;");
    } else {
      asm volatile("cp.async.wait_group 0;");
    }
    __syncthreads();

    const uint32_t* pAh = (const uint32_t*)(smf + b * 8192);
    const uint32_t* pAl = pAh + 2048;
    const uint32_t* pBh = pAh + 4096;
    const uint32_t* pBl = pAh + 6144;
#pragma unroll
    for (int kb = 0; kb < 2; kb++) {
      uint32_t ah[2][4], al[2][4];
#pragma unroll
      for (int mf = 0; mf < 2; mf++) {
        int r = wm * 32 + mf * 16 + gid;
        int o0 = kb * 1024 + r * 8;
        int o1 = kb * 1024 + (r + 8) * 8;
        ah[mf][0] = pAh[o0 + tig];     ah[mf][1] = pAh[o1 + tig];
        ah[mf][2] = pAh[o0 + 4 + tig]; ah[mf][3] = pAh[o1 + 4 + tig];
        al[mf][0] = pAl[o0 + tig];     al[mf][1] = pAl[o1 + tig];
        al[mf][2] = pAl[o0 + 4 + tig]; al[mf][3] = pAl[o1 + 4 + tig];
      }
      uint32_t bh[8][2], bl[8][2];
#pragma unroll
      for (int nf = 0; nf < 8; nf++) {
        int n = wn * 64 + nf * 8 + gid;
        int o = kb * 1024 + n * 8;
        bh[nf][0] = pBh[o + tig]; bh[nf][1] = pBh[o + 4 + tig];
        bl[nf][0] = pBl[o + tig]; bl[nf][1] = pBl[o + 4 + tig];
      }
#pragma unroll
      for (int mf = 0; mf < 2; mf++)
#pragma unroll
        for (int nf = 0; nf < 8; nf++) {
          mma_f16(acc[mf][nf], ah[mf], bh[nf]);
          mma_f16(acc[mf][nf], ah[mf], bl[nf]);
          mma_f16(acc[mf][nf], al[mf], bh[nf]);
        }
    }
    __syncthreads();
  }

  // ---- epilogue ----
  float ps[8][2], pq[8][2];
  if (STATS) {
#pragma unroll
    for (int nf = 0; nf < 8; nf++) {
      ps[nf][0] = ps[nf][1] = 0.f;
      pq[nf][0] = pq[nf][1] = 0.f;
    }
  }
#pragma unroll
  for (int mf = 0; mf < 2; mf++) {
    int r0 = brow + wm * 32 + mf * 16 + gid;
#pragma unroll
    for (int nf = 0; nf < 8; nf++) {
      int cg = bcol + wn * 64 + nf * 8 + 2 * tig;
      float b0 = bias[cg], b1 = bias[cg + 1];
      float v0 = acc[mf][nf][0] + b0, v1 = acc[mf][nf][1] + b1;
      float v2 = acc[mf][nf][2] + b0, v3 = acc[mf][nf][3] + b1;
      if (RELU) {
        v0 = fmaxf(v0, 0.f); v1 = fmaxf(v1, 0.f);
        v2 = fmaxf(v2, 0.f); v3 = fmaxf(v3, 0.f);
      }
      if (SPLIT_OUT) {
        __half h0, l0, h1, l1;
        if (r0 < N_NODES) {
          split1(v0, h0, l0); split1(v1, h1, l1);
          size_t i2 = (size_t)r0 * (NC / 2) + (cg >> 1);
          ((__half2*)g_th)[i2] = __halves2half2(h0, h1);
          ((__half2*)g_tl)[i2] = __halves2half2(l0, l1);
        }
        if (r0 + 8 < N_NODES) {
          split1(v2, h0, l0); split1(v3, h1, l1);
          size_t i2 = (size_t)(r0 + 8) * (NC / 2) + (cg >> 1);
          ((__half2*)g_th)[i2] = __halves2half2(h0, h1);
          ((__half2*)g_tl)[i2] = __halves2half2(l0, l1);
        }
      } else {
        if (r0 < N_NODES) *(float2*)(g_h + (size_t)r0 * NC + cg) = make_float2(v0, v1);
        if (r0 + 8 < N_NODES) *(float2*)(g_h + (size_t)(r0 + 8) * NC + cg) = make_float2(v2, v3);
      }
      if (STATS) {
        if (r0 < N_NODES) {
          ps[nf][0] += v0; pq[nf][0] += v0 * v0;
          ps[nf][1] += v1; pq[nf][1] += v1 * v1;
        }
        if (r0 + 8 < N_NODES) {
          ps[nf][0] += v2; pq[nf][0] += v2 * v2;
          ps[nf][1] += v3; pq[nf][1] += v3 * v3;
        }
      }
    }
  }

  if (STATS) {
    float* sm_s = smf;                    // [NC][32]
    float* sm_q = smf + NC * 32;          // [NC][32]
    __syncthreads();
    int unit = wm * 8 + gid;
#pragma unroll
    for (int nf = 0; nf < 8; nf++) {
      int cl = wn * 64 + nf * 8 + 2 * tig;
      sm_s[cl * 32 + unit]       = ps[nf][0];
      sm_s[(cl + 1) * 32 + unit] = ps[nf][1];
      sm_q[cl * 32 + unit]       = pq[nf][0];
      sm_q[(cl + 1) * 32 + unit] = pq[nf][1];
    }
    __syncthreads();
    if (tid < NC) {
      float s = 0.f, q = 0.f;
#pragma unroll
      for (int u = 0; u < 32; u++) {
        s += sm_s[tid * 32 + u];
        q += sm_q[tid * 32 + u];
      }
      atomicAdd(&g_colsum[bcol + tid], s);
      atomicAdd(&g_colsq[bcol + tid], q);
    }
  }
}

// ---------------- BatchNorm (+ELU): in-place g_h for l<4, out for l=4 ----------------
__global__ void k_bn(const float* __restrict__ gamma, const float* __restrict__ beta,
                     float* __restrict__ out_ext, int last) {
  int idx = blockIdx.x * 256 + threadIdx.x;  // float4 index
  if (idx >= N_NODES * (EMB / 4)) return;
  int c = (idx & 31) * 4;
  float4 v = *(const float4*)(g_h + (size_t)idx * 4);
  float vv[4] = {v.x, v.y, v.z, v.w};
  float o[4];
  const float inv = 1.f / (float)N_NODES;
#pragma unroll
  for (int j = 0; j < 4; j++) {
    int cc = c + j;
    float mu  = g_colsum[cc] * inv;
    float var = g_colsq[cc] * inv - mu * mu;
    float sc  = rsqrtf(var + 1e-5f) * gamma[cc];
    float xN  = (vv[j] - mu) * sc + beta[cc];
    if (!last) xN = xN > 0.f ? xN : expm1f(xN);
    o[j] = xN;
  }
  float* dst = last ? out_ext : g_h;
  *(float4*)(dst + (size_t)idx * 4) = *(float4*)&o[0];
}

// ---------------- launch ----------------
extern "C" void kernel_launch(void* const* d_in, const int* in_sizes, int n_in,
                              void* d_out, int out_size) {
  const float* x     = (const float*)d_in[0];
  const float* ea    = (const float*)d_in[1];
  const int*   ei    = (const int*)d_in[2];
  const float* Wx    = (const float*)d_in[3];
  const float* bx    = (const float*)d_in[4];
  const float* We    = (const float*)d_in[5];
  const float* be    = (const float*)d_in[6];
  const float* W1    = (const float*)d_in[7];
  const float* b1    = (const float*)d_in[8];
  const float* W2    = (const float*)d_in[9];
  const float* b2    = (const float*)d_in[10];
  const float* gamma = (const float*)d_in[11];
  const float* beta  = (const float*)d_in[12];
  float* out = (float*)d_out;

  const int SMEM = 65536;  // 2 buffers x 32KB
  static cudaStream_t s2;
  static cudaEvent_t  evA, evB;
  static int once = 0;
  if (!once) {
    cudaFuncSetAttribute(k_gemm_mma<128, 256, true,  true,  true,  false>,
                         cudaFuncAttributeMaxDynamicSharedMemorySize, SMEM);
    cudaFuncSetAttribute(k_gemm_mma<256, 128, false, false, false, true>,
                         cudaFuncAttributeMaxDynamicSharedMemorySize, SMEM);
    cudaStreamCreateWithFlags(&s2, cudaStreamNonBlocking);
    cudaEventCreateWithFlags(&evA, cudaEventDisableTiming);
    cudaEventCreateWithFlags(&evB, cudaEventDisableTiming);
    once = 1;
  }

  // ---- fork: weight-split + initial embedding on s2, CSR chain on main stream ----
  cudaEventRecord(evA, 0);
  cudaStreamWaitEvent(s2, evA, 0);
  k_prep_wi<<<1280 + 25000, 256, 0, s2>>>(W1, W2, x, Wx, bx);
  cudaEventRecord(evB, s2);

  k_zero_cnt<<<CDIV(N_NODES, 256), 256>>>();
  k_hist<<<CDIV(N_EDGES, 256), 256>>>(ei);
  k_scan1<<<SCAN_BLKS, 1024>>>();
  k_scan2<<<1, 32>>>();
  k_scan3<<<SCAN_BLKS, 1024>>>();
  k_fill<<<CDIV(N_EDGES, 256), 256>>>(ei);
  k_prep_graph<<<CDIV(N_NODES, 8), 256>>>(ei, ea);

  cudaStreamWaitEvent(0, evB, 0);   // join before the layer loop

  const int MT = CDIV(N_NODES, 128);  // 391
  dim3 g1(MT, 2);   // 2 x 128 -> 256 cols
  dim3 g2(MT, 1);   // 128 cols
  for (int l = 0; l < 5; l++) {
    k_gather<<<CDIV(N_NODES, 8), 256>>>(We + l * EFEAT * EMB, be + l * EFEAT * EMB);
    k_gemm_mma<128, 256, true,  true,  true,  false><<<g1, 256, SMEM>>>(l, b1 + l * HID);
    k_gemm_mma<256, 128, false, false, false, true ><<<g2, 256, SMEM>>>(l, b2 + l * EMB);
    k_bn<<<CDIV(N_NODES * 32, 256), 256>>>(gamma + l * EMB, beta + l * EMB,
                                           out, (l == 4) ? 1 : 0);
  }
}